// round 6
// baseline (speedup 1.0000x reference)
#include <cuda_runtime.h>
#include <cuda_bf16.h>
#include <math.h>
#include <stdint.h>

#define T_DIM 2048
#define B_DIM 4
#define D_DIM 1024
#define KEXT1 (3 * D_DIM)     // 3072 (bf16x3 path, G5 only)

// ---------------------------------------------------------------------------
// Device scratch
// ---------------------------------------------------------------------------
__device__ float         g_kv  [(size_t)T_DIM * B_DIM * 2 * D_DIM];
__device__ float         g_ctx [(size_t)T_DIM * B_DIM * D_DIM];
__device__ float         g_pscale[(size_t)B_DIM * T_DIM];
__device__ __nv_bfloat16 g_wo_ext  [(size_t)D_DIM * KEXT1];
__device__ __nv_bfloat16 g_ctx_ext [(size_t)T_DIM * B_DIM * KEXT1];
// int8 4-segment buffers (row length = 4*Klog)
__device__ int8_t g_feat_q[(size_t)T_DIM * B_DIM * 4 * D_DIM];   // A-side
__device__ int8_t g_wi_q  [(size_t)2 * D_DIM * 4 * D_DIM];       // B-side
__device__ int8_t g_q_q   [(size_t)B_DIM * T_DIM * 4 * D_DIM];   // A-side
__device__ int8_t g_k_q   [(size_t)B_DIM * T_DIM * 4 * D_DIM];   // B-side
__device__ int8_t g_p_q   [(size_t)B_DIM * T_DIM * 4 * T_DIM];   // A-side
__device__ int8_t g_vt_q  [(size_t)B_DIM * D_DIM * 4 * T_DIM];   // B-side

__device__ __forceinline__ uint32_t smem_u32(const void* p) {
    uint32_t a;
    asm("{ .reg .u64 t; cvta.to.shared.u64 t, %1; cvt.u32.u64 %0, t; }" : "=r"(a) : "l"(p));
    return a;
}

__device__ __forceinline__ void quant15(float x, float S, int& h, int& l) {
    int iq = __float2int_rn(x * S);
    iq = max(-16320, min(16255, iq));
    h = (iq + 64) >> 7;          // arithmetic shift: round-half-up(iq/128)
    l = iq - (h << 7);           // in [-64, 63]
}

// ---------------------------------------------------------------------------
// int8 NT GEMM: C[m][n] = cs(m) * sum_k Aq[m][k]*Bq[n][k] (+ bias[n])
// A rows = [h|h|l|l], B rows = [h|l|h|l], each segment Klog bytes.
// 3 phases: hh (K), hl+lh (2K), ll (K); fold weights 16384 / 128 / 1.
// Block 128(M) x 64(N), 256 threads, warp tile 32x32.
// ---------------------------------------------------------------------------
#define IBM 128
#define IBN 64
#define IPITCH 80       // 64 data bytes + 16 pad
#define IBUFA (IBM * IPITCH)
#define IBUFB (IBN * IPITCH)

__global__ __launch_bounds__(256) void gemm_imma(
    const int8_t* __restrict__ A, long sAz, int lda,
    const int8_t* __restrict__ B, long sBz, int ldb,
    float* __restrict__ C, long sCz, int ldc,
    const float* __restrict__ bias,
    const float* __restrict__ rs, long rsz,   // per-row scale (or null -> cscale)
    float cscale, int Klog)
{
    __shared__ int8_t As[2][IBM][IPITCH];
    __shared__ int8_t Bs[2][IBN][IPITCH];

    const int tid  = threadIdx.x;
    const int wid  = tid >> 5;
    const int lane = tid & 31;
    const int wm = (wid >> 1) * 32;
    const int wn = (wid & 1) * 32;
    const int m0 = blockIdx.y * IBM;
    const int n0 = blockIdx.x * IBN;

    A += (long)blockIdx.z * sAz;
    B += (long)blockIdx.z * sBz;
    C += (long)blockIdx.z * sCz;
    if (rs) rs += (long)blockIdx.z * rsz;

    const uint32_t sA = smem_u32(As);
    const uint32_t sB = smem_u32(Bs);

    auto load_tiles = [&](int buf, int koff) {
        #pragma unroll
        for (int h = 0; h < 2; h++) {
            const int row = (tid >> 2) + h * 64;
            const uint32_t da = sA + buf * IBUFA + row * IPITCH + (tid & 3) * 16;
            const int8_t* ga = A + (size_t)(m0 + row) * lda + koff + (tid & 3) * 16;
            asm volatile("cp.async.cg.shared.global [%0], [%1], 16;" :: "r"(da), "l"(ga));
        }
        {
            const int row = tid >> 2;   // 0..63
            const uint32_t db = sB + buf * IBUFB + row * IPITCH + (tid & 3) * 16;
            const int8_t* gb = B + (size_t)(n0 + row) * ldb + koff + (tid & 3) * 16;
            asm volatile("cp.async.cg.shared.global [%0], [%1], 16;" :: "r"(db), "l"(gb));
        }
        asm volatile("cp.async.commit_group;" ::: "memory");
    };

    float accf[2][4][4];
    int acc[2][4][4];
    #pragma unroll
    for (int i = 0; i < 2; i++)
        #pragma unroll
        for (int j = 0; j < 4; j++)
            #pragma unroll
            for (int r = 0; r < 4; r++) { accf[i][j][r] = 0.f; acc[i][j][r] = 0; }

    #pragma unroll
    for (int ph = 0; ph < 3; ph++) {
        const int koff0 = (ph == 0) ? 0 : (ph == 1 ? Klog : 3 * Klog);
        const int nkt = ((ph == 1) ? 2 * Klog : Klog) >> 6;
        const float w = (ph == 0) ? 16384.f : (ph == 1 ? 128.f : 1.f);

        load_tiles(0, koff0);
        int buf = 0;
        for (int kt = 0; kt < nkt; kt++) {
            if (kt + 1 < nkt) {
                load_tiles(buf ^ 1, koff0 + (kt + 1) * 64);
                asm volatile("cp.async.wait_group 1;" ::: "memory");
            } else {
                asm volatile("cp.async.wait_group 0;" ::: "memory");
            }
            __syncthreads();

            #pragma unroll
            for (int ks = 0; ks < 2; ks++) {
                uint32_t af[2][4];
                #pragma unroll
                for (int mt = 0; mt < 2; mt++) {
                    const int row = wm + mt * 16 + (lane & 15);
                    const uint32_t addr = sA + buf * IBUFA + row * IPITCH
                                        + ((lane >> 4) * 8 + ks * 16) * 2;
                    asm volatile("ldmatrix.sync.aligned.m8n8.x4.shared.b16 {%0,%1,%2,%3}, [%4];"
                                 : "=r"(af[mt][0]), "=r"(af[mt][1]), "=r"(af[mt][2]), "=r"(af[mt][3])
                                 : "r"(addr));
                }
                uint32_t bf[4][2];
                #pragma unroll
                for (int pr = 0; pr < 2; pr++) {
                    const int row = wn + pr * 16 + ((lane >> 4) & 1) * 8 + (lane & 7);
                    const uint32_t addr = sB + buf * IBUFB + row * IPITCH
                                        + (((lane >> 3) & 1) * 8 + ks * 16) * 2;
                    asm volatile("ldmatrix.sync.aligned.m8n8.x4.shared.b16 {%0,%1,%2,%3}, [%4];"
                                 : "=r"(bf[pr * 2][0]), "=r"(bf[pr * 2][1]),
                                   "=r"(bf[pr * 2 + 1][0]), "=r"(bf[pr * 2 + 1][1])
                                 : "r"(addr));
                }
                #pragma unroll
                for (int mt = 0; mt < 2; mt++)
                    #pragma unroll
                    for (int nt = 0; nt < 4; nt++) {
                        asm volatile(
                            "mma.sync.aligned.m16n8k32.row.col.s32.s8.s8.s32 "
                            "{%0,%1,%2,%3}, {%4,%5,%6,%7}, {%8,%9}, {%0,%1,%2,%3};"
                            : "+r"(acc[mt][nt][0]), "+r"(acc[mt][nt][1]),
                              "+r"(acc[mt][nt][2]), "+r"(acc[mt][nt][3])
                            : "r"(af[mt][0]), "r"(af[mt][1]), "r"(af[mt][2]), "r"(af[mt][3]),
                              "r"(bf[nt][0]), "r"(bf[nt][1]));
                    }
            }
            __syncthreads();
            buf ^= 1;
        }
        // fold this phase into fp32 and reset int bank
        #pragma unroll
        for (int i = 0; i < 2; i++)
            #pragma unroll
            for (int j = 0; j < 4; j++)
                #pragma unroll
                for (int r = 0; r < 4; r++) {
                    accf[i][j][r] += w * (float)acc[i][j][r];
                    acc[i][j][r] = 0;
                }
    }

    // Epilogue
    const int g  = lane >> 2;
    const int tg = lane & 3;
    #pragma unroll
    for (int mt = 0; mt < 2; mt++) {
        const int mr = m0 + wm + mt * 16 + g;
        const float s0 = rs ? rs[mr] : cscale;
        const float s1 = rs ? rs[mr + 8] : cscale;
        #pragma unroll
        for (int nt = 0; nt < 4; nt++) {
            const int n = n0 + wn + nt * 8 + 2 * tg;
            float b0 = 0.f, b1 = 0.f;
            if (bias) { b0 = bias[n]; b1 = bias[n + 1]; }
            float2 v0 = make_float2(accf[mt][nt][0] * s0 + b0, accf[mt][nt][1] * s0 + b1);
            float2 v1 = make_float2(accf[mt][nt][2] * s1 + b0, accf[mt][nt][3] * s1 + b1);
            *(float2*)(C + (size_t)mr * ldc + n) = v0;
            *(float2*)(C + (size_t)(mr + 8) * ldc + n) = v1;
        }
    }
}

// ---------------------------------------------------------------------------
// bf16 NT GEMM (R5, validated) -- used for out-projection only
// ---------------------------------------------------------------------------
#define BM 128
#define BN 128
#define BK 32
#define PITCH 40

__global__ __launch_bounds__(256) void gemm_mma(
    const __nv_bfloat16* __restrict__ A, long sAz, int lda,
    const __nv_bfloat16* __restrict__ B, long sBz, int ldb,
    float* __restrict__ C, long sCz, int ldc,
    const float* __restrict__ bias, int Kext)
{
    __shared__ __nv_bfloat16 As[2][BM][PITCH];
    __shared__ __nv_bfloat16 Bs[2][BN][PITCH];

    const int tid  = threadIdx.x;
    const int wid  = tid >> 5;
    const int lane = tid & 31;
    const int wm = (wid >> 2) * 64;
    const int wn = (wid & 3) * 32;
    const int m0 = blockIdx.y * BM;
    const int n0 = blockIdx.x * BN;

    A += (long)blockIdx.z * sAz;
    B += (long)blockIdx.z * sBz;
    C += (long)blockIdx.z * sCz;

    const uint32_t sA = smem_u32(As);
    const uint32_t sB = smem_u32(Bs);
    const uint32_t BUFA = (uint32_t)(BM * PITCH * 2);
    const uint32_t BUFB = (uint32_t)(BN * PITCH * 2);

    const int ld_row = tid >> 2;
    const int ld_c   = (tid & 3) * 16;

    auto load_tiles = [&](int buf, int k0) {
        #pragma unroll
        for (int h = 0; h < 2; h++) {
            const int row = ld_row + h * 64;
            const uint32_t da = sA + buf * BUFA + row * (PITCH * 2) + ld_c;
            const __nv_bfloat16* ga = A + (size_t)(m0 + row) * lda + k0 + (ld_c >> 1);
            asm volatile("cp.async.cg.shared.global [%0], [%1], 16;" :: "r"(da), "l"(ga));
            const uint32_t db = sB + buf * BUFB + row * (PITCH * 2) + ld_c;
            const __nv_bfloat16* gb = B + (size_t)(n0 + row) * ldb + k0 + (ld_c >> 1);
            asm volatile("cp.async.cg.shared.global [%0], [%1], 16;" :: "r"(db), "l"(gb));
        }
        asm volatile("cp.async.commit_group;" ::: "memory");
    };

    float acc[4][4][4];
    #pragma unroll
    for (int i = 0; i < 4; i++)
        #pragma unroll
        for (int j = 0; j < 4; j++)
            #pragma unroll
            for (int r = 0; r < 4; r++) acc[i][j][r] = 0.f;

    const int niter = Kext / BK;
    load_tiles(0, 0);
    int buf = 0;

    for (int kt = 0; kt < niter; kt++) {
        if (kt + 1 < niter) {
            load_tiles(buf ^ 1, (kt + 1) * BK);
            asm volatile("cp.async.wait_group 1;" ::: "memory");
        } else {
            asm volatile("cp.async.wait_group 0;" ::: "memory");
        }
        __syncthreads();

        #pragma unroll
        for (int k16 = 0; k16 < 2; k16++) {
            uint32_t af[4][4];
            #pragma unroll
            for (int mt = 0; mt < 4; mt++) {
                const int row = wm + mt * 16 + (lane & 15);
                const int col = (lane >> 4) * 8 + k16 * 16;
                const uint32_t addr = sA + buf * BUFA + row * (PITCH * 2) + col * 2;
                asm volatile("ldmatrix.sync.aligned.m8n8.x4.shared.b16 {%0,%1,%2,%3}, [%4];"
                             : "=r"(af[mt][0]), "=r"(af[mt][1]), "=r"(af[mt][2]), "=r"(af[mt][3])
                             : "r"(addr));
            }
            uint32_t bf[4][2];
            #pragma unroll
            for (int pr = 0; pr < 2; pr++) {
                const int row = wn + pr * 16 + ((lane >> 4) & 1) * 8 + (lane & 7);
                const int col = ((lane >> 3) & 1) * 8 + k16 * 16;
                const uint32_t addr = sB + buf * BUFB + row * (PITCH * 2) + col * 2;
                asm volatile("ldmatrix.sync.aligned.m8n8.x4.shared.b16 {%0,%1,%2,%3}, [%4];"
                             : "=r"(bf[pr * 2][0]), "=r"(bf[pr * 2][1]),
                               "=r"(bf[pr * 2 + 1][0]), "=r"(bf[pr * 2 + 1][1])
                             : "r"(addr));
            }
            #pragma unroll
            for (int mt = 0; mt < 4; mt++)
                #pragma unroll
                for (int nt = 0; nt < 4; nt++) {
                    asm volatile(
                        "mma.sync.aligned.m16n8k16.row.col.f32.bf16.bf16.f32 "
                        "{%0,%1,%2,%3}, {%4,%5,%6,%7}, {%8,%9}, {%0,%1,%2,%3};"
                        : "+f"(acc[mt][nt][0]), "+f"(acc[mt][nt][1]),
                          "+f"(acc[mt][nt][2]), "+f"(acc[mt][nt][3])
                        : "r"(af[mt][0]), "r"(af[mt][1]), "r"(af[mt][2]), "r"(af[mt][3]),
                          "r"(bf[nt][0]), "r"(bf[nt][1]));
                }
        }
        __syncthreads();
        buf ^= 1;
    }

    const int g  = lane >> 2;
    const int tg = lane & 3;
    #pragma unroll
    for (int mt = 0; mt < 4; mt++) {
        const int mrow0 = m0 + wm + mt * 16 + g;
        #pragma unroll
        for (int nt = 0; nt < 4; nt++) {
            const int n = n0 + wn + nt * 8 + 2 * tg;
            float b0 = 0.f, b1 = 0.f;
            if (bias) { b0 = bias[n]; b1 = bias[n + 1]; }
            float2 v0 = make_float2(acc[mt][nt][0] + b0, acc[mt][nt][1] + b1);
            float2 v1 = make_float2(acc[mt][nt][2] + b0, acc[mt][nt][3] + b1);
            *(float2*)(C + (size_t)mrow0 * ldc + n) = v0;
            *(float2*)(C + (size_t)(mrow0 + 8) * ldc + n) = v1;
        }
    }
}

// ---------------------------------------------------------------------------
// fp32 -> int8 (h,l) quantization into 4-segment layout.
//   sideA=1: [h|h|l|l]   sideA=0: [h|l|h|l]
// ---------------------------------------------------------------------------
__global__ __launch_bounds__(256) void quant_conv(
    const float* __restrict__ src, long sb, long srs,
    int8_t* __restrict__ dst, int rows, int K, float S, int sideA)
{
    const long idx = (long)blockIdx.x * 256 + threadIdx.x;
    const int r = (int)(idx / K);
    const int k = (int)(idx % K);
    if (r >= rows) return;
    const float x = src[(long)blockIdx.z * sb + (long)r * srs + k];
    int h, l;
    quant15(x, S, h, l);
    int8_t* d = dst + (size_t)blockIdx.z * rows * 4 * K + (size_t)r * 4 * K + k;
    if (sideA) {
        d[0] = (int8_t)h; d[K] = (int8_t)h; d[2 * K] = (int8_t)l; d[3 * K] = (int8_t)l;
    } else {
        d[0] = (int8_t)h; d[K] = (int8_t)l; d[2 * K] = (int8_t)h; d[3 * K] = (int8_t)l;
    }
}

// ---------------------------------------------------------------------------
// V transpose + quantize (B-side): kv V half [s][b][d] -> vt_q[b][d][h|l|h|l over s]
// ---------------------------------------------------------------------------
__global__ __launch_bounds__(256) void vtq_conv(
    const float* __restrict__ kv, int8_t* __restrict__ vt)
{
    __shared__ float tile[32][33];
    const int b = blockIdx.z;
    const int s0 = blockIdx.x * 32;
    const int d0 = blockIdx.y * 32;
    const int tx = threadIdx.x & 31;
    const int ty = threadIdx.x >> 5;

    #pragma unroll
    for (int r = 0; r < 4; r++) {
        const int s = s0 + ty + r * 8;
        tile[ty + r * 8][tx] = kv[(size_t)s * (B_DIM * 2 * D_DIM) + b * (2 * D_DIM) + D_DIM + d0 + tx];
    }
    __syncthreads();
    #pragma unroll
    for (int r = 0; r < 4; r++) {
        const int d = d0 + ty + r * 8;
        const int s = s0 + tx;
        int h, l;
        quant15(tile[tx][ty + r * 8], 2000.f, h, l);
        int8_t* dst = vt + (size_t)b * D_DIM * 4 * T_DIM + (size_t)d * 4 * T_DIM + s;
        dst[0] = (int8_t)h;
        dst[T_DIM] = (int8_t)l;
        dst[2 * T_DIM] = (int8_t)h;
        dst[3 * T_DIM] = (int8_t)l;
    }
}

// ---------------------------------------------------------------------------
// bf16x3 split (G5 path only).  modeA: [hi|hi|lo], else [hi|lo|hi]
// ---------------------------------------------------------------------------
__global__ __launch_bounds__(256) void split_conv(
    const float* __restrict__ src, long sb, long srs,
    __nv_bfloat16* __restrict__ dst, int rows, int K, float scale, int modeA)
{
    const long idx = (long)blockIdx.x * 256 + threadIdx.x;
    const int r = (int)(idx / K);
    const int k = (int)(idx % K);
    if (r >= rows) return;
    const float x = src[(long)blockIdx.z * sb + (long)r * srs + k] * scale;
    const __nv_bfloat16 hi = __float2bfloat16_rn(x);
    const __nv_bfloat16 lo = __float2bfloat16_rn(x - __bfloat162float(hi));
    __nv_bfloat16* d = dst + (size_t)blockIdx.z * rows * 3 * K + (size_t)r * 3 * K + k;
    d[0] = hi;
    d[K] = modeA ? hi : lo;
    d[2 * K] = modeA ? lo : hi;
}

// ---------------------------------------------------------------------------
// Softmax + fused P quantization (A-side layout) + per-row scale
// ---------------------------------------------------------------------------
__global__ __launch_bounds__(256) void softmax_pq_kernel(
    float* __restrict__ P, int8_t* __restrict__ pq_all, float* __restrict__ pscale)
{
    const long R = blockIdx.x;                    // b*T + t
    float* row = P + R * T_DIM;
    int8_t* pq = pq_all + R * (4 * T_DIM);
    const int tid = threadIdx.x;

    float vals[8];
    float mx = -INFINITY;
    #pragma unroll
    for (int i = 0; i < 8; i++) { vals[i] = row[tid + i * 256]; mx = fmaxf(mx, vals[i]); }

    __shared__ float red[256];
    red[tid] = mx; __syncthreads();
    for (int s = 128; s > 0; s >>= 1) { if (tid < s) red[tid] = fmaxf(red[tid], red[tid + s]); __syncthreads(); }
    mx = red[0]; __syncthreads();

    float sum = 0.f;
    #pragma unroll
    for (int i = 0; i < 8; i++) { vals[i] = __expf(vals[i] - mx); sum += vals[i]; }
    red[tid] = sum; __syncthreads();
    for (int s = 128; s > 0; s >>= 1) { if (tid < s) red[tid] += red[tid + s]; __syncthreads(); }
    const float inv = 1.0f / red[0];

    #pragma unroll
    for (int i = 0; i < 8; i++) {
        const int col = tid + i * 256;
        row[col] = vals[i] * inv;
        // quantize unnormalized exp (in [0,1]); scale 16000
        int iq = __float2int_rn(vals[i] * 16000.f);
        const int h = (iq + 64) >> 7;
        const int l = iq - (h << 7);
        pq[col] = (int8_t)h;
        pq[T_DIM + col] = (int8_t)h;
        pq[2 * T_DIM + col] = (int8_t)l;
        pq[3 * T_DIM + col] = (int8_t)l;
    }
    if (tid == 0) pscale[R] = inv / (16000.f * 2000.f);
}

// ---------------------------------------------------------------------------
extern "C" void kernel_launch(void* const* d_in, const int* in_sizes, int n_in,
                              void* d_out, int out_size)
{
    const float* query = (const float*)d_in[0];
    const float* feat  = (const float*)d_in[1];
    const float* Wi    = (const float*)d_in[2];
    const float* bi    = (const float*)d_in[3];
    const float* Wo    = (const float*)d_in[4];
    const float* bo    = (const float*)d_in[5];

    float* out = (float*)d_out;
    float* attn_out = out;
    float* aw = out + (size_t)T_DIM * B_DIM * D_DIM;

    float *kv, *ctx, *pscale;
    __nv_bfloat16 *wo_e, *ctx_e;
    int8_t *feat_q, *wi_q, *q_q, *k_q, *p_q, *vt_q;
    cudaGetSymbolAddress((void**)&kv, g_kv);
    cudaGetSymbolAddress((void**)&ctx, g_ctx);
    cudaGetSymbolAddress((void**)&pscale, g_pscale);
    cudaGetSymbolAddress((void**)&wo_e, g_wo_ext);
    cudaGetSymbolAddress((void**)&ctx_e, g_ctx_ext);
    cudaGetSymbolAddress((void**)&feat_q, g_feat_q);
    cudaGetSymbolAddress((void**)&wi_q, g_wi_q);
    cudaGetSymbolAddress((void**)&q_q, g_q_q);
    cudaGetSymbolAddress((void**)&k_q, g_k_q);
    cudaGetSymbolAddress((void**)&p_q, g_p_q);
    cudaGetSymbolAddress((void**)&vt_q, g_vt_q);

    const long TT = (long)T_DIM * T_DIM;
    // epilogue scales: 1/(Sa*Sb)  (G2 additionally folds qk scaling 1/32)
    const float cs_g1 = 1.0f / (2000.f * 64000.f);            // feat x Wi
    const float cs_g2 = 0.03125f / (2000.f * 2000.f);         // q x k

    // --- input quantization
    quant_conv<<<dim3((T_DIM * B_DIM * D_DIM) / 256, 1, 1), 256>>>(feat, 0, D_DIM, feat_q, T_DIM * B_DIM, D_DIM, 2000.f, 1);
    quant_conv<<<dim3((2 * D_DIM * D_DIM) / 256, 1, 1), 256>>>(Wi, 0, D_DIM, wi_q, 2 * D_DIM, D_DIM, 64000.f, 0);
    quant_conv<<<dim3((T_DIM * D_DIM) / 256, 1, B_DIM), 256>>>(query, D_DIM, (long)B_DIM * D_DIM, q_q, T_DIM, D_DIM, 2000.f, 1);
    split_conv<<<dim3((D_DIM * D_DIM) / 256, 1, 1), 256>>>(Wo, 0, D_DIM, wo_e, D_DIM, D_DIM, 1.f, 0);

    // 1) KV projection: M=8192, N=2048, Klog=1024
    gemm_imma<<<dim3(2 * D_DIM / IBN, T_DIM * B_DIM / IBM, 1), 256>>>(
        feat_q, 0, 4 * D_DIM, wi_q, 0, 4 * D_DIM,
        kv, 0, 2 * D_DIM, bi, nullptr, 0, cs_g1, D_DIM);

    // k quantize + V transpose/quantize
    quant_conv<<<dim3((T_DIM * D_DIM) / 256, 1, B_DIM), 256>>>(kv, 2 * D_DIM, (long)B_DIM * 2 * D_DIM, k_q, T_DIM, D_DIM, 2000.f, 0);
    vtq_conv<<<dim3(T_DIM / 32, D_DIM / 32, B_DIM), 256>>>(kv, vt_q);

    // 2) scores: M=2048, N=2048, Klog=1024, batched over B
    gemm_imma<<<dim3(T_DIM / IBN, T_DIM / IBM, B_DIM), 256>>>(
        q_q, (long)T_DIM * 4 * D_DIM, 4 * D_DIM,
        k_q, (long)T_DIM * 4 * D_DIM, 4 * D_DIM,
        aw, TT, T_DIM, nullptr, nullptr, 0, cs_g2, D_DIM);

    // 3) softmax (+ fused P quantization)
    softmax_pq_kernel<<<B_DIM * T_DIM, 256>>>(aw, p_q, pscale);

    // 4) context: M=2048, N=1024, Klog=2048, per-row scale
    gemm_imma<<<dim3(D_DIM / IBN, T_DIM / IBM, B_DIM), 256>>>(
        p_q, (long)T_DIM * 4 * T_DIM, 4 * T_DIM,
        vt_q, (long)D_DIM * 4 * T_DIM, 4 * T_DIM,
        ctx, D_DIM, B_DIM * D_DIM, nullptr, pscale, T_DIM, 0.f, T_DIM);

    // ctx -> bf16x3, out projection (bf16 path)
    split_conv<<<dim3((T_DIM * B_DIM * D_DIM) / 256, 1, 1), 256>>>(ctx, 0, D_DIM, ctx_e, T_DIM * B_DIM, D_DIM, 1.f, 1);
    gemm_mma<<<dim3(D_DIM / BN, T_DIM * B_DIM / BM, 1), 256>>>(
        ctx_e, 0, KEXT1, wo_e, 0, KEXT1, attn_out, 0, D_DIM, bo, KEXT1);
}

// round 7
// speedup vs baseline: 2.1707x; 2.1707x over previous
#include <cuda_runtime.h>
#include <cuda_bf16.h>
#include <math.h>
#include <stdint.h>

#define T_DIM 2048
#define B_DIM 4
#define D_DIM 1024
#define KEXT1 (3 * D_DIM)     // 3072
#define KEXT2 (3 * T_DIM)     // 6144

// ---------------------------------------------------------------------------
// Device scratch
// ---------------------------------------------------------------------------
__device__ float         g_v   [(size_t)T_DIM * B_DIM * D_DIM];      // [s*B+b][d]
__device__ __nv_bfloat16 g_feat_ext[(size_t)T_DIM * B_DIM * KEXT1];
__device__ __nv_bfloat16 g_wi_ext  [(size_t)2 * D_DIM * KEXT1];
__device__ __nv_bfloat16 g_wo_ext  [(size_t)D_DIM * KEXT1];
__device__ __nv_bfloat16 g_q_ext   [(size_t)B_DIM * T_DIM * KEXT1];
__device__ __nv_bfloat16 g_k_ext   [(size_t)B_DIM * T_DIM * KEXT1];
__device__ __nv_bfloat16 g_p_ext   [(size_t)B_DIM * T_DIM * KEXT2];
__device__ __nv_bfloat16 g_vt_ext  [(size_t)B_DIM * D_DIM * KEXT2];
__device__ __nv_bfloat16 g_ctx_ext [(size_t)T_DIM * B_DIM * KEXT1];

__device__ __forceinline__ uint32_t smem_u32(const void* p) {
    uint32_t a;
    asm("{ .reg .u64 t; cvta.to.shared.u64 t, %1; cvt.u32.u64 %0, t; }" : "=r"(a) : "l"(p));
    return a;
}

// ---------------------------------------------------------------------------
// bf16 NT GEMM via mma.sync (validated R5 core).
//   OMODE 0: C[m][n] = acc + bias[n]      (fp32, float2 stores)
//   OMODE 1: KV projection epilogue: n<D -> k_ext bf16x3 B-mode [hi|lo|hi],
//            n>=D -> fp32 V buffer aux2[row][n-D]. bias applied to both.
//   OMODE 2: ctx epilogue: ctx_ext bf16x3 A-mode [hi|hi|lo], rows t*B+z.
// Block 128x128x32, 256 threads, warp grid 2(m) x 4(n).
// ---------------------------------------------------------------------------
#define BM 128
#define BN 128
#define BK 32
#define PITCH 40   // bf16 elems per SMEM row (64B data + 16B pad)

template <int OMODE>
__global__ __launch_bounds__(256) void gemm_mma(
    const __nv_bfloat16* __restrict__ A, long sAz, int lda,
    const __nv_bfloat16* __restrict__ B, long sBz, int ldb,
    float* __restrict__ C, long sCz, int ldc,
    const float* __restrict__ bias,
    __nv_bfloat16* __restrict__ aux, float* __restrict__ aux2, int Kext)
{
    __shared__ __nv_bfloat16 As[2][BM][PITCH];
    __shared__ __nv_bfloat16 Bs[2][BN][PITCH];

    const int tid  = threadIdx.x;
    const int wid  = tid >> 5;
    const int lane = tid & 31;
    const int wm = (wid >> 2) * 64;
    const int wn = (wid & 3) * 32;
    const int m0 = blockIdx.y * BM;
    const int n0 = blockIdx.x * BN;

    A += (long)blockIdx.z * sAz;
    B += (long)blockIdx.z * sBz;
    if (OMODE == 0) C += (long)blockIdx.z * sCz;

    const uint32_t sA = smem_u32(As);
    const uint32_t sB = smem_u32(Bs);
    const uint32_t BUFA = (uint32_t)(BM * PITCH * 2);
    const uint32_t BUFB = (uint32_t)(BN * PITCH * 2);

    const int ld_row = tid >> 2;
    const int ld_c   = (tid & 3) * 16;

    auto load_tiles = [&](int buf, int k0) {
        #pragma unroll
        for (int h = 0; h < 2; h++) {
            const int row = ld_row + h * 64;
            const uint32_t da = sA + buf * BUFA + row * (PITCH * 2) + ld_c;
            const __nv_bfloat16* ga = A + (size_t)(m0 + row) * lda + k0 + (ld_c >> 1);
            asm volatile("cp.async.cg.shared.global [%0], [%1], 16;" :: "r"(da), "l"(ga));
            const uint32_t db = sB + buf * BUFB + row * (PITCH * 2) + ld_c;
            const __nv_bfloat16* gb = B + (size_t)(n0 + row) * ldb + k0 + (ld_c >> 1);
            asm volatile("cp.async.cg.shared.global [%0], [%1], 16;" :: "r"(db), "l"(gb));
        }
        asm volatile("cp.async.commit_group;" ::: "memory");
    };

    float acc[4][4][4];
    #pragma unroll
    for (int i = 0; i < 4; i++)
        #pragma unroll
        for (int j = 0; j < 4; j++)
            #pragma unroll
            for (int r = 0; r < 4; r++) acc[i][j][r] = 0.f;

    const int niter = Kext / BK;
    load_tiles(0, 0);
    int buf = 0;

    for (int kt = 0; kt < niter; kt++) {
        if (kt + 1 < niter) {
            load_tiles(buf ^ 1, (kt + 1) * BK);
            asm volatile("cp.async.wait_group 1;" ::: "memory");
        } else {
            asm volatile("cp.async.wait_group 0;" ::: "memory");
        }
        __syncthreads();

        #pragma unroll
        for (int k16 = 0; k16 < 2; k16++) {
            uint32_t af[4][4];
            #pragma unroll
            for (int mt = 0; mt < 4; mt++) {
                const int row = wm + mt * 16 + (lane & 15);
                const int col = (lane >> 4) * 8 + k16 * 16;
                const uint32_t addr = sA + buf * BUFA + row * (PITCH * 2) + col * 2;
                asm volatile("ldmatrix.sync.aligned.m8n8.x4.shared.b16 {%0,%1,%2,%3}, [%4];"
                             : "=r"(af[mt][0]), "=r"(af[mt][1]), "=r"(af[mt][2]), "=r"(af[mt][3])
                             : "r"(addr));
            }
            uint32_t bf[4][2];
            #pragma unroll
            for (int pr = 0; pr < 2; pr++) {
                const int row = wn + pr * 16 + ((lane >> 4) & 1) * 8 + (lane & 7);
                const int col = ((lane >> 3) & 1) * 8 + k16 * 16;
                const uint32_t addr = sB + buf * BUFB + row * (PITCH * 2) + col * 2;
                asm volatile("ldmatrix.sync.aligned.m8n8.x4.shared.b16 {%0,%1,%2,%3}, [%4];"
                             : "=r"(bf[pr * 2][0]), "=r"(bf[pr * 2][1]),
                               "=r"(bf[pr * 2 + 1][0]), "=r"(bf[pr * 2 + 1][1])
                             : "r"(addr));
            }
            #pragma unroll
            for (int mt = 0; mt < 4; mt++)
                #pragma unroll
                for (int nt = 0; nt < 4; nt++) {
                    asm volatile(
                        "mma.sync.aligned.m16n8k16.row.col.f32.bf16.bf16.f32 "
                        "{%0,%1,%2,%3}, {%4,%5,%6,%7}, {%8,%9}, {%0,%1,%2,%3};"
                        : "+f"(acc[mt][nt][0]), "+f"(acc[mt][nt][1]),
                          "+f"(acc[mt][nt][2]), "+f"(acc[mt][nt][3])
                        : "r"(af[mt][0]), "r"(af[mt][1]), "r"(af[mt][2]), "r"(af[mt][3]),
                          "r"(bf[nt][0]), "r"(bf[nt][1]));
                }
        }
        __syncthreads();
        buf ^= 1;
    }

    // ---------------- epilogue ----------------
    const int g  = lane >> 2;
    const int tg = lane & 3;

    if (OMODE == 0) {
        #pragma unroll
        for (int mt = 0; mt < 4; mt++) {
            const int mrow0 = m0 + wm + mt * 16 + g;
            #pragma unroll
            for (int nt = 0; nt < 4; nt++) {
                const int n = n0 + wn + nt * 8 + 2 * tg;
                float b0 = 0.f, b1 = 0.f;
                if (bias) { b0 = bias[n]; b1 = bias[n + 1]; }
                float2 v0 = make_float2(acc[mt][nt][0] + b0, acc[mt][nt][1] + b1);
                float2 v1 = make_float2(acc[mt][nt][2] + b0, acc[mt][nt][3] + b1);
                *(float2*)(C + (size_t)mrow0 * ldc + n) = v0;
                *(float2*)(C + (size_t)(mrow0 + 8) * ldc + n) = v1;
            }
        }
    } else {
        #pragma unroll
        for (int mt = 0; mt < 4; mt++) {
            const int mrow0 = m0 + wm + mt * 16 + g;
            #pragma unroll
            for (int nt = 0; nt < 4; nt++) {
                const int nb = n0 + wn + nt * 8 + 2 * tg;
                #pragma unroll
                for (int r = 0; r < 4; r++) {
                    const int row = mrow0 + (r >> 1) * 8;
                    const int n = nb + (r & 1);
                    float v = acc[mt][nt][r];
                    if (bias) v += bias[n];
                    if (OMODE == 1) {
                        if (n < D_DIM) {
                            const int b = row & (B_DIM - 1);
                            const int s = row >> 2;
                            const __nv_bfloat16 hi = __float2bfloat16_rn(v);
                            const __nv_bfloat16 lo = __float2bfloat16_rn(v - __bfloat162float(hi));
                            __nv_bfloat16* d = aux + ((size_t)b * T_DIM + s) * KEXT1 + n;
                            d[0] = hi; d[D_DIM] = lo; d[2 * D_DIM] = hi;   // B-mode
                        } else {
                            aux2[(size_t)row * D_DIM + (n - D_DIM)] = v;
                        }
                    } else {  // OMODE == 2: ctx
                        const __nv_bfloat16 hi = __float2bfloat16_rn(v);
                        const __nv_bfloat16 lo = __float2bfloat16_rn(v - __bfloat162float(hi));
                        __nv_bfloat16* d = aux + ((size_t)row * B_DIM + blockIdx.z) * KEXT1 + n;
                        d[0] = hi; d[D_DIM] = hi; d[2 * D_DIM] = lo;       // A-mode
                    }
                }
            }
        }
    }
}

// ---------------------------------------------------------------------------
// fp32 -> bf16 hi/lo 3-segment split.  modeA: [hi|hi|lo], else [hi|lo|hi]
// ---------------------------------------------------------------------------
__global__ __launch_bounds__(256) void split_conv(
    const float* __restrict__ src, long sb, long srs,
    __nv_bfloat16* __restrict__ dst, int rows, int K, float scale, int modeA)
{
    const long idx = (long)blockIdx.x * 256 + threadIdx.x;
    const int r = (int)(idx / K);
    const int k = (int)(idx % K);
    if (r >= rows) return;
    const float x = src[(long)blockIdx.z * sb + (long)r * srs + k] * scale;
    const __nv_bfloat16 hi = __float2bfloat16_rn(x);
    const __nv_bfloat16 lo = __float2bfloat16_rn(x - __bfloat162float(hi));
    __nv_bfloat16* d = dst + (size_t)blockIdx.z * rows * 3 * K + (size_t)r * 3 * K + k;
    d[0] = hi;
    d[K] = modeA ? hi : lo;
    d[2 * K] = modeA ? lo : hi;
}

// ---------------------------------------------------------------------------
// V transpose + B-mode split: g_v[s*B+b][d] -> vt[b][d][hi(s)|lo(s)|hi(s)]
// ---------------------------------------------------------------------------
__global__ __launch_bounds__(256) void vt_conv(
    const float* __restrict__ V, __nv_bfloat16* __restrict__ vt)
{
    __shared__ float tile[32][33];
    const int b = blockIdx.z;
    const int s0 = blockIdx.x * 32;
    const int d0 = blockIdx.y * 32;
    const int tx = threadIdx.x & 31;
    const int ty = threadIdx.x >> 5;

    #pragma unroll
    for (int r = 0; r < 4; r++) {
        const int s = s0 + ty + r * 8;
        tile[ty + r * 8][tx] = V[((size_t)s * B_DIM + b) * D_DIM + d0 + tx];
    }
    __syncthreads();
    #pragma unroll
    for (int r = 0; r < 4; r++) {
        const int d = d0 + ty + r * 8;
        const int s = s0 + tx;
        const float x = tile[tx][ty + r * 8];
        const __nv_bfloat16 hi = __float2bfloat16_rn(x);
        const __nv_bfloat16 lo = __float2bfloat16_rn(x - __bfloat162float(hi));
        __nv_bfloat16* dst = vt + (size_t)b * D_DIM * KEXT2 + (size_t)d * KEXT2 + s;
        dst[0] = hi;
        dst[T_DIM] = lo;
        dst[2 * T_DIM] = hi;
    }
}

// ---------------------------------------------------------------------------
// Softmax (in place) + fused P bf16x3 A-mode emission
// ---------------------------------------------------------------------------
__global__ __launch_bounds__(256) void softmax_p_kernel(
    float* __restrict__ P, __nv_bfloat16* __restrict__ p_ext)
{
    const long R = blockIdx.x;                 // b*T + t
    float* row = P + R * T_DIM;
    __nv_bfloat16* pq = p_ext + R * (size_t)KEXT2;
    const int tid = threadIdx.x;

    float vals[8];
    float mx = -INFINITY;
    #pragma unroll
    for (int i = 0; i < 8; i++) { vals[i] = row[tid + i * 256]; mx = fmaxf(mx, vals[i]); }

    __shared__ float red[256];
    red[tid] = mx; __syncthreads();
    for (int s = 128; s > 0; s >>= 1) { if (tid < s) red[tid] = fmaxf(red[tid], red[tid + s]); __syncthreads(); }
    mx = red[0]; __syncthreads();

    float sum = 0.f;
    #pragma unroll
    for (int i = 0; i < 8; i++) { vals[i] = __expf(vals[i] - mx); sum += vals[i]; }
    red[tid] = sum; __syncthreads();
    for (int s = 128; s > 0; s >>= 1) { if (tid < s) red[tid] += red[tid + s]; __syncthreads(); }
    const float inv = 1.0f / red[0];

    #pragma unroll
    for (int i = 0; i < 8; i++) {
        const int col = tid + i * 256;
        const float p = vals[i] * inv;
        row[col] = p;
        const __nv_bfloat16 hi = __float2bfloat16_rn(p);
        const __nv_bfloat16 lo = __float2bfloat16_rn(p - __bfloat162float(hi));
        pq[col] = hi;
        pq[T_DIM + col] = hi;
        pq[2 * T_DIM + col] = lo;
    }
}

// ---------------------------------------------------------------------------
extern "C" void kernel_launch(void* const* d_in, const int* in_sizes, int n_in,
                              void* d_out, int out_size)
{
    const float* query = (const float*)d_in[0];
    const float* feat  = (const float*)d_in[1];
    const float* Wi    = (const float*)d_in[2];
    const float* bi    = (const float*)d_in[3];
    const float* Wo    = (const float*)d_in[4];
    const float* bo    = (const float*)d_in[5];

    float* out = (float*)d_out;
    float* attn_out = out;
    float* aw = out + (size_t)T_DIM * B_DIM * D_DIM;

    float *gv;
    __nv_bfloat16 *feat_e, *wi_e, *wo_e, *q_e, *k_e, *p_e, *vt_e, *ctx_e;
    cudaGetSymbolAddress((void**)&gv, g_v);
    cudaGetSymbolAddress((void**)&feat_e, g_feat_ext);
    cudaGetSymbolAddress((void**)&wi_e, g_wi_ext);
    cudaGetSymbolAddress((void**)&wo_e, g_wo_ext);
    cudaGetSymbolAddress((void**)&q_e, g_q_ext);
    cudaGetSymbolAddress((void**)&k_e, g_k_ext);
    cudaGetSymbolAddress((void**)&p_e, g_p_ext);
    cudaGetSymbolAddress((void**)&vt_e, g_vt_ext);
    cudaGetSymbolAddress((void**)&ctx_e, g_ctx_ext);

    const float scale = 0.03125f;
    const long TT = (long)T_DIM * T_DIM;

    // input conversions
    split_conv<<<dim3((T_DIM * B_DIM * D_DIM) / 256, 1, 1), 256>>>(feat, 0, D_DIM, feat_e, T_DIM * B_DIM, D_DIM, 1.f, 1);
    split_conv<<<dim3((2 * D_DIM * D_DIM) / 256, 1, 1), 256>>>(Wi, 0, D_DIM, wi_e, 2 * D_DIM, D_DIM, 1.f, 0);
    split_conv<<<dim3((D_DIM * D_DIM) / 256, 1, 1), 256>>>(Wo, 0, D_DIM, wo_e, D_DIM, D_DIM, 1.f, 0);
    split_conv<<<dim3((T_DIM * D_DIM) / 256, 1, B_DIM), 256>>>(query, D_DIM, (long)B_DIM * D_DIM, q_e, T_DIM, D_DIM, scale, 1);

    // 1) KV projection, fused K-split + V extract (M=8192, N=2048, K'=3072)
    gemm_mma<1><<<dim3(2 * D_DIM / BN, T_DIM * B_DIM / BM, 1), 256>>>(
        feat_e, 0, KEXT1, wi_e, 0, KEXT1,
        nullptr, 0, 0, bi, k_e, gv, KEXT1);

    // V transpose + split
    vt_conv<<<dim3(T_DIM / 32, D_DIM / 32, B_DIM), 256>>>(gv, vt_e);

    // 2) scores (M=2048, N=2048, K'=3072) batched over B
    gemm_mma<0><<<dim3(T_DIM / BN, T_DIM / BM, B_DIM), 256>>>(
        q_e, (long)T_DIM * KEXT1, KEXT1, k_e, (long)T_DIM * KEXT1, KEXT1,
        aw, TT, T_DIM, nullptr, nullptr, nullptr, KEXT1);

    // 3) softmax + fused P split
    softmax_p_kernel<<<B_DIM * T_DIM, 256>>>(aw, p_e);

    // 4) context, fused ctx-split (M=2048, N=1024, K'=6144) batched
    gemm_mma<2><<<dim3(D_DIM / BN, T_DIM / BM, B_DIM), 256>>>(
        p_e, (long)T_DIM * KEXT2, KEXT2, vt_e, (long)D_DIM * KEXT2, KEXT2,
        nullptr, 0, 0, nullptr, ctx_e, nullptr, KEXT2);

    // 5) out projection (M=8192, N=1024, K'=3072)
    gemm_mma<0><<<dim3(D_DIM / BN, T_DIM * B_DIM / BM, 1), 256>>>(
        ctx_e, 0, KEXT1, wo_e, 0, KEXT1,
        attn_out, 0, D_DIM, bo, nullptr, nullptr, KEXT1);
}

// round 8
// speedup vs baseline: 2.3133x; 1.0657x over previous
#include <cuda_runtime.h>
#include <cuda_bf16.h>
#include <math.h>
#include <stdint.h>

#define T_DIM 2048
#define B_DIM 4
#define D_DIM 1024
#define KEXT1 (3 * D_DIM)     // 3072
#define KEXT2 (3 * T_DIM)     // 6144

// ---------------------------------------------------------------------------
// Device scratch
// ---------------------------------------------------------------------------
__device__ float         g_kv  [(size_t)T_DIM * B_DIM * 2 * D_DIM];
__device__ float         g_ctx [(size_t)T_DIM * B_DIM * D_DIM];
__device__ __nv_bfloat16 g_feat_ext[(size_t)T_DIM * B_DIM * KEXT1];
__device__ __nv_bfloat16 g_wi_ext  [(size_t)2 * D_DIM * KEXT1];
__device__ __nv_bfloat16 g_wo_ext  [(size_t)D_DIM * KEXT1];
__device__ __nv_bfloat16 g_q_ext   [(size_t)B_DIM * T_DIM * KEXT1];
__device__ __nv_bfloat16 g_k_ext   [(size_t)B_DIM * T_DIM * KEXT1];
__device__ __nv_bfloat16 g_p_ext   [(size_t)B_DIM * T_DIM * KEXT2];
__device__ __nv_bfloat16 g_vt_ext  [(size_t)B_DIM * D_DIM * KEXT2];
__device__ __nv_bfloat16 g_ctx_ext [(size_t)T_DIM * B_DIM * KEXT1];

__device__ __forceinline__ uint32_t smem_u32(const void* p) {
    uint32_t a;
    asm("{ .reg .u64 t; cvta.to.shared.u64 t, %1; cvt.u32.u64 %0, t; }" : "=r"(a) : "l"(p));
    return a;
}

// ---------------------------------------------------------------------------
// bf16 NT GEMM via mma.sync -- 3-stage cp.async pipeline, 1 sync per k-tile.
//   C[m][n] = sum_k A[m][k]*B[n][k] (+ bias[n])
// Block 128x128x32, 256 threads, warp grid 2(m) x 4(n), warp tile 64x32.
// ---------------------------------------------------------------------------
#define BM 128
#define BN 128
#define BK 32
#define PITCH 40                      // bf16 elems per SMEM row (64B data + 16B pad)
#define ABYTES (BM * PITCH * 2)       // 10240
#define BBYTES (BN * PITCH * 2)       // 10240
#define STAGE_BYTES (ABYTES + BBYTES) // 20480
#define GEMM_SMEM (3 * STAGE_BYTES)   // 61440

__global__ __launch_bounds__(256, 2) void gemm_mma(
    const __nv_bfloat16* __restrict__ A, long sAz, int lda,
    const __nv_bfloat16* __restrict__ B, long sBz, int ldb,
    float* __restrict__ C, long sCz, int ldc,
    const float* __restrict__ bias, int Kext)
{
    extern __shared__ char smem[];
    const uint32_t sbase = smem_u32(smem);

    const int tid  = threadIdx.x;
    const int wid  = tid >> 5;
    const int lane = tid & 31;
    const int wm = (wid >> 2) * 64;
    const int wn = (wid & 3) * 32;
    const int m0 = blockIdx.y * BM;
    const int n0 = blockIdx.x * BN;

    A += (long)blockIdx.z * sAz;
    B += (long)blockIdx.z * sBz;
    C += (long)blockIdx.z * sCz;

    const int ld_row = tid >> 2;        // 0..63
    const int ld_c   = (tid & 3) * 16;  // byte col

    auto load_tiles = [&](int st, int k0) {
        const uint32_t a0 = sbase + st * STAGE_BYTES;
        const uint32_t b0 = a0 + ABYTES;
        #pragma unroll
        for (int h = 0; h < 2; h++) {
            const int row = ld_row + h * 64;
            const uint32_t da = a0 + row * (PITCH * 2) + ld_c;
            const __nv_bfloat16* ga = A + (size_t)(m0 + row) * lda + k0 + (ld_c >> 1);
            asm volatile("cp.async.cg.shared.global [%0], [%1], 16;" :: "r"(da), "l"(ga));
            const uint32_t db = b0 + row * (PITCH * 2) + ld_c;
            const __nv_bfloat16* gb = B + (size_t)(n0 + row) * ldb + k0 + (ld_c >> 1);
            asm volatile("cp.async.cg.shared.global [%0], [%1], 16;" :: "r"(db), "l"(gb));
        }
        asm volatile("cp.async.commit_group;" ::: "memory");
    };

    float acc[4][4][4];
    #pragma unroll
    for (int i = 0; i < 4; i++)
        #pragma unroll
        for (int j = 0; j < 4; j++)
            #pragma unroll
            for (int r = 0; r < 4; r++) acc[i][j][r] = 0.f;

    const int niter = Kext / BK;
    load_tiles(0, 0);
    load_tiles(1, BK);

    int st = 0;   // stage of current k-tile
    for (int kt = 0; kt < niter; kt++) {
        if (kt + 1 < niter) {
            asm volatile("cp.async.wait_group 1;" ::: "memory");
        } else {
            asm volatile("cp.async.wait_group 0;" ::: "memory");
        }
        __syncthreads();
        if (kt + 2 < niter) {
            int st2 = st + 2; if (st2 >= 3) st2 -= 3;
            load_tiles(st2, (kt + 2) * BK);
        }

        const uint32_t sA = sbase + st * STAGE_BYTES;
        const uint32_t sB = sA + ABYTES;

        #pragma unroll
        for (int k16 = 0; k16 < 2; k16++) {
            uint32_t af[4][4];
            #pragma unroll
            for (int mt = 0; mt < 4; mt++) {
                const int row = wm + mt * 16 + (lane & 15);
                const int col = (lane >> 4) * 8 + k16 * 16;
                const uint32_t addr = sA + row * (PITCH * 2) + col * 2;
                asm volatile("ldmatrix.sync.aligned.m8n8.x4.shared.b16 {%0,%1,%2,%3}, [%4];"
                             : "=r"(af[mt][0]), "=r"(af[mt][1]), "=r"(af[mt][2]), "=r"(af[mt][3])
                             : "r"(addr));
            }
            uint32_t bf[4][2];
            #pragma unroll
            for (int pr = 0; pr < 2; pr++) {
                const int row = wn + pr * 16 + ((lane >> 4) & 1) * 8 + (lane & 7);
                const int col = ((lane >> 3) & 1) * 8 + k16 * 16;
                const uint32_t addr = sB + row * (PITCH * 2) + col * 2;
                asm volatile("ldmatrix.sync.aligned.m8n8.x4.shared.b16 {%0,%1,%2,%3}, [%4];"
                             : "=r"(bf[pr * 2][0]), "=r"(bf[pr * 2][1]),
                               "=r"(bf[pr * 2 + 1][0]), "=r"(bf[pr * 2 + 1][1])
                             : "r"(addr));
            }
            #pragma unroll
            for (int mt = 0; mt < 4; mt++)
                #pragma unroll
                for (int nt = 0; nt < 4; nt++) {
                    asm volatile(
                        "mma.sync.aligned.m16n8k16.row.col.f32.bf16.bf16.f32 "
                        "{%0,%1,%2,%3}, {%4,%5,%6,%7}, {%8,%9}, {%0,%1,%2,%3};"
                        : "+f"(acc[mt][nt][0]), "+f"(acc[mt][nt][1]),
                          "+f"(acc[mt][nt][2]), "+f"(acc[mt][nt][3])
                        : "r"(af[mt][0]), "r"(af[mt][1]), "r"(af[mt][2]), "r"(af[mt][3]),
                          "r"(bf[nt][0]), "r"(bf[nt][1]));
                }
        }
        if (++st == 3) st = 0;
    }

    const int g  = lane >> 2;
    const int tg = lane & 3;
    #pragma unroll
    for (int mt = 0; mt < 4; mt++) {
        const int mrow0 = m0 + wm + mt * 16 + g;
        #pragma unroll
        for (int nt = 0; nt < 4; nt++) {
            const int n = n0 + wn + nt * 8 + 2 * tg;
            float b0 = 0.f, b1 = 0.f;
            if (bias) { b0 = bias[n]; b1 = bias[n + 1]; }
            float2 v0 = make_float2(acc[mt][nt][0] + b0, acc[mt][nt][1] + b1);
            float2 v1 = make_float2(acc[mt][nt][2] + b0, acc[mt][nt][3] + b1);
            *(float2*)(C + (size_t)mrow0 * ldc + n) = v0;
            *(float2*)(C + (size_t)(mrow0 + 8) * ldc + n) = v1;
        }
    }
}

// ---------------------------------------------------------------------------
// fp32 -> bf16 hi/lo split, 3-segment K layout.  modeA: [hi|hi|lo], else [hi|lo|hi]
// ---------------------------------------------------------------------------
__global__ __launch_bounds__(256) void split_conv(
    const float* __restrict__ src, long sb, long srs,
    __nv_bfloat16* __restrict__ dst, int rows, int K, float scale, int modeA)
{
    const long idx = (long)blockIdx.x * 256 + threadIdx.x;
    const int r = (int)(idx / K);
    const int k = (int)(idx % K);
    if (r >= rows) return;
    const float x = src[(long)blockIdx.z * sb + (long)r * srs + k] * scale;
    const __nv_bfloat16 hi = __float2bfloat16_rn(x);
    const __nv_bfloat16 lo = __float2bfloat16_rn(x - __bfloat162float(hi));
    __nv_bfloat16* d = dst + (size_t)blockIdx.z * rows * 3 * K + (size_t)r * 3 * K + k;
    d[0] = hi;
    d[K] = modeA ? hi : lo;
    d[2 * K] = modeA ? lo : hi;
}

// ---------------------------------------------------------------------------
// V transpose + B-mode split: kv V part [s][b][d] -> vt[b][d][hi(s)|lo(s)|hi(s)]
// ---------------------------------------------------------------------------
__global__ __launch_bounds__(256) void vt_conv(
    const float* __restrict__ kv, __nv_bfloat16* __restrict__ vt)
{
    __shared__ float tile[32][33];
    const int b = blockIdx.z;
    const int s0 = blockIdx.x * 32;
    const int d0 = blockIdx.y * 32;
    const int tx = threadIdx.x & 31;
    const int ty = threadIdx.x >> 5;

    #pragma unroll
    for (int r = 0; r < 4; r++) {
        const int s = s0 + ty + r * 8;
        tile[ty + r * 8][tx] = kv[(size_t)s * (B_DIM * 2 * D_DIM) + b * (2 * D_DIM) + D_DIM + d0 + tx];
    }
    __syncthreads();
    #pragma unroll
    for (int r = 0; r < 4; r++) {
        const int d = d0 + ty + r * 8;
        const int s = s0 + tx;
        const float x = tile[tx][ty + r * 8];
        const __nv_bfloat16 hi = __float2bfloat16_rn(x);
        const __nv_bfloat16 lo = __float2bfloat16_rn(x - __bfloat162float(hi));
        __nv_bfloat16* dst = vt + (size_t)b * D_DIM * KEXT2 + (size_t)d * KEXT2 + s;
        dst[0] = hi;
        dst[T_DIM] = lo;
        dst[2 * T_DIM] = hi;
    }
}

// ---------------------------------------------------------------------------
__global__ __launch_bounds__(256) void softmax_kernel(float* __restrict__ P)
{
    float* row = P + (long)blockIdx.x * T_DIM;
    const int tid = threadIdx.x;
    float vals[8];
    float mx = -INFINITY;
    #pragma unroll
    for (int i = 0; i < 8; i++) { vals[i] = row[tid + i * 256]; mx = fmaxf(mx, vals[i]); }

    __shared__ float red[256];
    red[tid] = mx; __syncthreads();
    for (int s = 128; s > 0; s >>= 1) { if (tid < s) red[tid] = fmaxf(red[tid], red[tid + s]); __syncthreads(); }
    mx = red[0]; __syncthreads();

    float sum = 0.f;
    #pragma unroll
    for (int i = 0; i < 8; i++) { vals[i] = __expf(vals[i] - mx); sum += vals[i]; }
    red[tid] = sum; __syncthreads();
    for (int s = 128; s > 0; s >>= 1) { if (tid < s) red[tid] += red[tid + s]; __syncthreads(); }
    const float inv = 1.0f / red[0];
    #pragma unroll
    for (int i = 0; i < 8; i++) row[tid + i * 256] = vals[i] * inv;
}

// ---------------------------------------------------------------------------
extern "C" void kernel_launch(void* const* d_in, const int* in_sizes, int n_in,
                              void* d_out, int out_size)
{
    const float* query = (const float*)d_in[0];
    const float* feat  = (const float*)d_in[1];
    const float* Wi    = (const float*)d_in[2];
    const float* bi    = (const float*)d_in[3];
    const float* Wo    = (const float*)d_in[4];
    const float* bo    = (const float*)d_in[5];

    float* out = (float*)d_out;
    float* attn_out = out;
    float* aw = out + (size_t)T_DIM * B_DIM * D_DIM;

    float *kv, *ctx;
    __nv_bfloat16 *feat_e, *wi_e, *wo_e, *q_e, *k_e, *p_e, *vt_e, *ctx_e;
    cudaGetSymbolAddress((void**)&kv, g_kv);
    cudaGetSymbolAddress((void**)&ctx, g_ctx);
    cudaGetSymbolAddress((void**)&feat_e, g_feat_ext);
    cudaGetSymbolAddress((void**)&wi_e, g_wi_ext);
    cudaGetSymbolAddress((void**)&wo_e, g_wo_ext);
    cudaGetSymbolAddress((void**)&q_e, g_q_ext);
    cudaGetSymbolAddress((void**)&k_e, g_k_ext);
    cudaGetSymbolAddress((void**)&p_e, g_p_ext);
    cudaGetSymbolAddress((void**)&vt_e, g_vt_ext);
    cudaGetSymbolAddress((void**)&ctx_e, g_ctx_ext);

    cudaFuncSetAttribute(gemm_mma, cudaFuncAttributeMaxDynamicSharedMemorySize, GEMM_SMEM);

    const float scale = 0.03125f;
    const long TT = (long)T_DIM * T_DIM;

    split_conv<<<dim3((T_DIM * B_DIM * D_DIM) / 256, 1, 1), 256>>>(feat, 0, D_DIM, feat_e, T_DIM * B_DIM, D_DIM, 1.f, 1);
    split_conv<<<dim3((2 * D_DIM * D_DIM) / 256, 1, 1), 256>>>(Wi, 0, D_DIM, wi_e, 2 * D_DIM, D_DIM, 1.f, 0);
    split_conv<<<dim3((D_DIM * D_DIM) / 256, 1, 1), 256>>>(Wo, 0, D_DIM, wo_e, D_DIM, D_DIM, 1.f, 0);
    split_conv<<<dim3((T_DIM * D_DIM) / 256, 1, B_DIM), 256>>>(query, D_DIM, (long)B_DIM * D_DIM, q_e, T_DIM, D_DIM, scale, 1);

    // 1) KV projection (M=8192, N=2048, K'=3072)
    gemm_mma<<<dim3(2 * D_DIM / BN, T_DIM * B_DIM / BM, 1), 256, GEMM_SMEM>>>(
        feat_e, 0, KEXT1, wi_e, 0, KEXT1, kv, 0, 2 * D_DIM, bi, KEXT1);

    split_conv<<<dim3((T_DIM * D_DIM) / 256, 1, B_DIM), 256>>>(kv, 2 * D_DIM, (long)B_DIM * 2 * D_DIM, k_e, T_DIM, D_DIM, 1.f, 0);
    vt_conv<<<dim3(T_DIM / 32, D_DIM / 32, B_DIM), 256>>>(kv, vt_e);

    // 2) scores (M=2048, N=2048, K'=3072) batched over B
    gemm_mma<<<dim3(T_DIM / BN, T_DIM / BM, B_DIM), 256, GEMM_SMEM>>>(
        q_e, (long)T_DIM * KEXT1, KEXT1, k_e, (long)T_DIM * KEXT1, KEXT1,
        aw, TT, T_DIM, nullptr, KEXT1);

    // 3) softmax
    softmax_kernel<<<B_DIM * T_DIM, 256>>>(aw);

    split_conv<<<dim3((int)(TT / 256), 1, B_DIM), 256>>>(aw, TT, T_DIM, p_e, T_DIM, T_DIM, 1.f, 1);

    // 4) context (M=2048, N=1024, K'=6144) batched
    gemm_mma<<<dim3(D_DIM / BN, T_DIM / BM, B_DIM), 256, GEMM_SMEM>>>(
        p_e, (long)T_DIM * KEXT2, KEXT2, vt_e, (long)D_DIM * KEXT2, KEXT2,
        ctx, D_DIM, B_DIM * D_DIM, nullptr, KEXT2);

    split_conv<<<dim3((T_DIM * B_DIM * D_DIM) / 256, 1, 1), 256>>>(ctx, 0, D_DIM, ctx_e, T_DIM * B_DIM, D_DIM, 1.f, 1);

    // 5) out projection (M=8192, N=1024, K'=3072)
    gemm_mma<<<dim3(D_DIM / BN, T_DIM * B_DIM / BM, 1), 256, GEMM_SMEM>>>(
        ctx_e, 0, KEXT1, wo_e, 0, KEXT1, attn_out, 0, D_DIM, bo, KEXT1);
}

// round 10
// speedup vs baseline: 2.9298x; 1.2665x over previous
#include <cuda_runtime.h>
#include <cuda_bf16.h>
#include <cuda_fp16.h>
#include <math.h>
#include <stdint.h>
#include <type_traits>

#define T_DIM 2048
#define B_DIM 4
#define D_DIM 1024
#define KEXT1 (3 * D_DIM)     // 3072

// ---------------------------------------------------------------------------
// Device scratch
// ---------------------------------------------------------------------------
__device__ float         g_kv  [(size_t)T_DIM * B_DIM * 2 * D_DIM];
__device__ float         g_ctx [(size_t)T_DIM * B_DIM * D_DIM];
__device__ __nv_bfloat16 g_feat_ext[(size_t)T_DIM * B_DIM * KEXT1];
__device__ __nv_bfloat16 g_wi_ext  [(size_t)2 * D_DIM * KEXT1];
__device__ __nv_bfloat16 g_wo_ext  [(size_t)D_DIM * KEXT1];
__device__ __nv_bfloat16 g_q_ext   [(size_t)B_DIM * T_DIM * KEXT1];
__device__ __nv_bfloat16 g_k_ext   [(size_t)B_DIM * T_DIM * KEXT1];
__device__ __nv_bfloat16 g_ctx_ext [(size_t)T_DIM * B_DIM * KEXT1];
__device__ half          g_p_h    [(size_t)B_DIM * T_DIM * T_DIM];   // [b][t][s]
__device__ half          g_vt_h   [(size_t)B_DIM * D_DIM * T_DIM];   // [b][d][s]

__device__ __forceinline__ uint32_t smem_u32(const void* p) {
    uint32_t a;
    asm("{ .reg .u64 t; cvta.to.shared.u64 t, %1; cvt.u32.u64 %0, t; }" : "=r"(a) : "l"(p));
    return a;
}

// ---------------------------------------------------------------------------
// NT GEMM via mma.sync, templated on operand type (bf16 or fp16), fp32 accum.
// 3-stage cp.async pipeline, 1 sync per k-tile. Block 128x128x32, 256 thr.
// ---------------------------------------------------------------------------
#define BM 128
#define BN 128
#define BK 32
#define PITCH 40                      // 16b elems per SMEM row (64B data + 16B pad)
#define ABYTES (BM * PITCH * 2)
#define BBYTES (BN * PITCH * 2)
#define STAGE_BYTES (ABYTES + BBYTES)
#define GEMM_SMEM (3 * STAGE_BYTES)   // 61440

template <typename TIN>
__global__ __launch_bounds__(256, 2) void gemm_mma(
    const TIN* __restrict__ A, long sAz, int lda,
    const TIN* __restrict__ B, long sBz, int ldb,
    float* __restrict__ C, long sCz, int ldc,
    const float* __restrict__ bias, int Kext)
{
    extern __shared__ char smem[];
    const uint32_t sbase = smem_u32(smem);

    const int tid  = threadIdx.x;
    const int wid  = tid >> 5;
    const int lane = tid & 31;
    const int wm = (wid >> 2) * 64;
    const int wn = (wid & 3) * 32;
    const int m0 = blockIdx.y * BM;
    const int n0 = blockIdx.x * BN;

    A += (long)blockIdx.z * sAz;
    B += (long)blockIdx.z * sBz;
    C += (long)blockIdx.z * sCz;

    const int ld_row = tid >> 2;
    const int ld_c   = (tid & 3) * 16;

    auto load_tiles = [&](int st, int k0) {
        const uint32_t a0 = sbase + st * STAGE_BYTES;
        const uint32_t b0 = a0 + ABYTES;
        #pragma unroll
        for (int h = 0; h < 2; h++) {
            const int row = ld_row + h * 64;
            const uint32_t da = a0 + row * (PITCH * 2) + ld_c;
            const TIN* ga = A + (size_t)(m0 + row) * lda + k0 + (ld_c >> 1);
            asm volatile("cp.async.cg.shared.global [%0], [%1], 16;" :: "r"(da), "l"(ga));
            const uint32_t db = b0 + row * (PITCH * 2) + ld_c;
            const TIN* gb = B + (size_t)(n0 + row) * ldb + k0 + (ld_c >> 1);
            asm volatile("cp.async.cg.shared.global [%0], [%1], 16;" :: "r"(db), "l"(gb));
        }
        asm volatile("cp.async.commit_group;" ::: "memory");
    };

    float acc[4][4][4];
    #pragma unroll
    for (int i = 0; i < 4; i++)
        #pragma unroll
        for (int j = 0; j < 4; j++)
            #pragma unroll
            for (int r = 0; r < 4; r++) acc[i][j][r] = 0.f;

    const int niter = Kext / BK;
    load_tiles(0, 0);
    load_tiles(1, BK);

    int st = 0;
    for (int kt = 0; kt < niter; kt++) {
        if (kt + 1 < niter) {
            asm volatile("cp.async.wait_group 1;" ::: "memory");
        } else {
            asm volatile("cp.async.wait_group 0;" ::: "memory");
        }
        __syncthreads();
        if (kt + 2 < niter) {
            int st2 = st + 2; if (st2 >= 3) st2 -= 3;
            load_tiles(st2, (kt + 2) * BK);
        }

        const uint32_t sA = sbase + st * STAGE_BYTES;
        const uint32_t sB = sA + ABYTES;

        #pragma unroll
        for (int k16 = 0; k16 < 2; k16++) {
            uint32_t af[4][4];
            #pragma unroll
            for (int mt = 0; mt < 4; mt++) {
                const int row = wm + mt * 16 + (lane & 15);
                const int col = (lane >> 4) * 8 + k16 * 16;
                const uint32_t addr = sA + row * (PITCH * 2) + col * 2;
                asm volatile("ldmatrix.sync.aligned.m8n8.x4.shared.b16 {%0,%1,%2,%3}, [%4];"
                             : "=r"(af[mt][0]), "=r"(af[mt][1]), "=r"(af[mt][2]), "=r"(af[mt][3])
                             : "r"(addr));
            }
            uint32_t bf[4][2];
            #pragma unroll
            for (int pr = 0; pr < 2; pr++) {
                const int row = wn + pr * 16 + ((lane >> 4) & 1) * 8 + (lane & 7);
                const int col = ((lane >> 3) & 1) * 8 + k16 * 16;
                const uint32_t addr = sB + row * (PITCH * 2) + col * 2;
                asm volatile("ldmatrix.sync.aligned.m8n8.x4.shared.b16 {%0,%1,%2,%3}, [%4];"
                             : "=r"(bf[pr * 2][0]), "=r"(bf[pr * 2][1]),
                               "=r"(bf[pr * 2 + 1][0]), "=r"(bf[pr * 2 + 1][1])
                             : "r"(addr));
            }
            #pragma unroll
            for (int mt = 0; mt < 4; mt++)
                #pragma unroll
                for (int nt = 0; nt < 4; nt++) {
                    if constexpr (std::is_same<TIN, half>::value) {
                        asm volatile(
                            "mma.sync.aligned.m16n8k16.row.col.f32.f16.f16.f32 "
                            "{%0,%1,%2,%3}, {%4,%5,%6,%7}, {%8,%9}, {%0,%1,%2,%3};"
                            : "+f"(acc[mt][nt][0]), "+f"(acc[mt][nt][1]),
                              "+f"(acc[mt][nt][2]), "+f"(acc[mt][nt][3])
                            : "r"(af[mt][0]), "r"(af[mt][1]), "r"(af[mt][2]), "r"(af[mt][3]),
                              "r"(bf[nt][0]), "r"(bf[nt][1]));
                    } else {
                        asm volatile(
                            "mma.sync.aligned.m16n8k16.row.col.f32.bf16.bf16.f32 "
                            "{%0,%1,%2,%3}, {%4,%5,%6,%7}, {%8,%9}, {%0,%1,%2,%3};"
                            : "+f"(acc[mt][nt][0]), "+f"(acc[mt][nt][1]),
                              "+f"(acc[mt][nt][2]), "+f"(acc[mt][nt][3])
                            : "r"(af[mt][0]), "r"(af[mt][1]), "r"(af[mt][2]), "r"(af[mt][3]),
                              "r"(bf[nt][0]), "r"(bf[nt][1]));
                    }
                }
        }
        if (++st == 3) st = 0;
    }

    const int g  = lane >> 2;
    const int tg = lane & 3;
    #pragma unroll
    for (int mt = 0; mt < 4; mt++) {
        const int mrow0 = m0 + wm + mt * 16 + g;
        #pragma unroll
        for (int nt = 0; nt < 4; nt++) {
            const int n = n0 + wn + nt * 8 + 2 * tg;
            float b0 = 0.f, b1 = 0.f;
            if (bias) { b0 = bias[n]; b1 = bias[n + 1]; }
            float2 v0 = make_float2(acc[mt][nt][0] + b0, acc[mt][nt][1] + b1);
            float2 v1 = make_float2(acc[mt][nt][2] + b0, acc[mt][nt][3] + b1);
            *(float2*)(C + (size_t)mrow0 * ldc + n) = v0;
            *(float2*)(C + (size_t)(mrow0 + 8) * ldc + n) = v1;
        }
    }
}

// ---------------------------------------------------------------------------
// fp32 -> bf16 hi/lo split, 3-segment K layout.  modeA: [hi|hi|lo], else [hi|lo|hi]
// ---------------------------------------------------------------------------
__global__ __launch_bounds__(256) void split_conv(
    const float* __restrict__ src, long sb, long srs,
    __nv_bfloat16* __restrict__ dst, int rows, int K, float scale, int modeA)
{
    const long idx = (long)blockIdx.x * 256 + threadIdx.x;
    const int r = (int)(idx / K);
    const int k = (int)(idx % K);
    if (r >= rows) return;
    const float x = src[(long)blockIdx.z * sb + (long)r * srs + k] * scale;
    const __nv_bfloat16 hi = __float2bfloat16_rn(x);
    const __nv_bfloat16 lo = __float2bfloat16_rn(x - __bfloat162float(hi));
    __nv_bfloat16* d = dst + (size_t)blockIdx.z * rows * 3 * K + (size_t)r * 3 * K + k;
    d[0] = hi;
    d[K] = modeA ? hi : lo;
    d[2 * K] = modeA ? lo : hi;
}

// ---------------------------------------------------------------------------
// V transpose to fp16: kv V part [s][b][d] -> vt_h[b][d][s]
// ---------------------------------------------------------------------------
__global__ __launch_bounds__(256) void vt_conv_h(
    const float* __restrict__ kv, half* __restrict__ vt)
{
    __shared__ float tile[32][33];
    const int b = blockIdx.z;
    const int s0 = blockIdx.x * 32;
    const int d0 = blockIdx.y * 32;
    const int tx = threadIdx.x & 31;
    const int ty = threadIdx.x >> 5;

    #pragma unroll
    for (int r = 0; r < 4; r++) {
        const int s = s0 + ty + r * 8;
        tile[ty + r * 8][tx] = kv[(size_t)s * (B_DIM * 2 * D_DIM) + b * (2 * D_DIM) + D_DIM + d0 + tx];
    }
    __syncthreads();
    #pragma unroll
    for (int r = 0; r < 4; r++) {
        const int d = d0 + ty + r * 8;
        const int s = s0 + tx;
        vt[(size_t)b * D_DIM * T_DIM + (size_t)d * T_DIM + s] = __float2half_rn(tile[tx][ty + r * 8]);
    }
}

// ---------------------------------------------------------------------------
// Softmax (in place, fp32) + fused fp16 P emission (coalesced)
// ---------------------------------------------------------------------------
__global__ __launch_bounds__(256) void softmax_p_kernel(
    float* __restrict__ P, half* __restrict__ ph_all)
{
    const long R = blockIdx.x;                  // b*T + t
    float* row = P + R * T_DIM;
    half* ph = ph_all + R * (size_t)T_DIM;
    const int tid = threadIdx.x;

    float vals[8];
    float mx = -INFINITY;
    #pragma unroll
    for (int i = 0; i < 8; i++) { vals[i] = row[tid + i * 256]; mx = fmaxf(mx, vals[i]); }

    __shared__ float red[256];
    red[tid] = mx; __syncthreads();
    for (int s = 128; s > 0; s >>= 1) { if (tid < s) red[tid] = fmaxf(red[tid], red[tid + s]); __syncthreads(); }
    mx = red[0]; __syncthreads();

    float sum = 0.f;
    #pragma unroll
    for (int i = 0; i < 8; i++) { vals[i] = __expf(vals[i] - mx); sum += vals[i]; }
    red[tid] = sum; __syncthreads();
    for (int s = 128; s > 0; s >>= 1) { if (tid < s) red[tid] += red[tid + s]; __syncthreads(); }
    const float inv = 1.0f / red[0];

    #pragma unroll
    for (int i = 0; i < 8; i++) {
        const int col = tid + i * 256;
        const float p = vals[i] * inv;
        row[col] = p;
        ph[col] = __float2half_rn(p);
    }
}

// ---------------------------------------------------------------------------
extern "C" void kernel_launch(void* const* d_in, const int* in_sizes, int n_in,
                              void* d_out, int out_size)
{
    const float* query = (const float*)d_in[0];
    const float* feat  = (const float*)d_in[1];
    const float* Wi    = (const float*)d_in[2];
    const float* bi    = (const float*)d_in[3];
    const float* Wo    = (const float*)d_in[4];
    const float* bo    = (const float*)d_in[5];

    float* out = (float*)d_out;
    float* attn_out = out;
    float* aw = out + (size_t)T_DIM * B_DIM * D_DIM;

    float *kv, *ctx;
    __nv_bfloat16 *feat_e, *wi_e, *wo_e, *q_e, *k_e, *ctx_e;
    half *p_h, *vt_h;
    cudaGetSymbolAddress((void**)&kv, g_kv);
    cudaGetSymbolAddress((void**)&ctx, g_ctx);
    cudaGetSymbolAddress((void**)&feat_e, g_feat_ext);
    cudaGetSymbolAddress((void**)&wi_e, g_wi_ext);
    cudaGetSymbolAddress((void**)&wo_e, g_wo_ext);
    cudaGetSymbolAddress((void**)&q_e, g_q_ext);
    cudaGetSymbolAddress((void**)&k_e, g_k_ext);
    cudaGetSymbolAddress((void**)&ctx_e, g_ctx_ext);
    cudaGetSymbolAddress((void**)&p_h, g_p_h);
    cudaGetSymbolAddress((void**)&vt_h, g_vt_h);

    cudaFuncSetAttribute(gemm_mma<__nv_bfloat16>, cudaFuncAttributeMaxDynamicSharedMemorySize, GEMM_SMEM);
    cudaFuncSetAttribute(gemm_mma<half>, cudaFuncAttributeMaxDynamicSharedMemorySize, GEMM_SMEM);

    const float scale = 0.03125f;
    const long TT = (long)T_DIM * T_DIM;

    split_conv<<<dim3((T_DIM * B_DIM * D_DIM) / 256, 1, 1), 256>>>(feat, 0, D_DIM, feat_e, T_DIM * B_DIM, D_DIM, 1.f, 1);
    split_conv<<<dim3((2 * D_DIM * D_DIM) / 256, 1, 1), 256>>>(Wi, 0, D_DIM, wi_e, 2 * D_DIM, D_DIM, 1.f, 0);
    split_conv<<<dim3((D_DIM * D_DIM) / 256, 1, 1), 256>>>(Wo, 0, D_DIM, wo_e, D_DIM, D_DIM, 1.f, 0);
    split_conv<<<dim3((T_DIM * D_DIM) / 256, 1, B_DIM), 256>>>(query, D_DIM, (long)B_DIM * D_DIM, q_e, T_DIM, D_DIM, scale, 1);

    // 1) KV projection (M=8192, N=2048, K'=3072)  bf16x3
    gemm_mma<__nv_bfloat16><<<dim3(2 * D_DIM / BN, T_DIM * B_DIM / BM, 1), 256, GEMM_SMEM>>>(
        feat_e, 0, KEXT1, wi_e, 0, KEXT1, kv, 0, 2 * D_DIM, bi, KEXT1);

    split_conv<<<dim3((T_DIM * D_DIM) / 256, 1, B_DIM), 256>>>(kv, 2 * D_DIM, (long)B_DIM * 2 * D_DIM, k_e, T_DIM, D_DIM, 1.f, 0);
    vt_conv_h<<<dim3(T_DIM / 32, D_DIM / 32, B_DIM), 256>>>(kv, vt_h);

    // 2) scores (M=2048, N=2048, K'=3072)  bf16x3, batched over B
    gemm_mma<__nv_bfloat16><<<dim3(T_DIM / BN, T_DIM / BM, B_DIM), 256, GEMM_SMEM>>>(
        q_e, (long)T_DIM * KEXT1, KEXT1, k_e, (long)T_DIM * KEXT1, KEXT1,
        aw, TT, T_DIM, nullptr, KEXT1);

    // 3) softmax + fused fp16 P emission
    softmax_p_kernel<<<B_DIM * T_DIM, 256>>>(aw, p_h);

    // 4) context (M=2048, N=1024, K=2048)  fp16 single, batched
    gemm_mma<half><<<dim3(D_DIM / BN, T_DIM / BM, B_DIM), 256, GEMM_SMEM>>>(
        p_h, TT, T_DIM, vt_h, (long)D_DIM * T_DIM, T_DIM,
        ctx, D_DIM, B_DIM * D_DIM, nullptr, T_DIM);

    split_conv<<<dim3((T_DIM * B_DIM * D_DIM) / 256, 1, 1), 256>>>(ctx, 0, D_DIM, ctx_e, T_DIM * B_DIM, D_DIM, 1.f, 1);

    // 5) out projection (M=8192, N=1024, K'=3072)  bf16x3
    gemm_mma<__nv_bfloat16><<<dim3(D_DIM / BN, T_DIM * B_DIM / BM, 1), 256, GEMM_SMEM>>>(
        ctx_e, 0, KEXT1, wo_e, 0, KEXT1, attn_out, 0, D_DIM, bo, KEXT1);
}

// round 11
// speedup vs baseline: 3.8969x; 1.3301x over previous
#include <cuda_runtime.h>
#include <cuda_fp16.h>
#include <math.h>
#include <stdint.h>

#define T_DIM 2048
#define B_DIM 4
#define D_DIM 1024
#define KX (2 * D_DIM)        // 2048 -- unified K' for every GEMM

// ---------------------------------------------------------------------------
// Device scratch
// ---------------------------------------------------------------------------
__device__ float g_kv  [(size_t)T_DIM * B_DIM * 2 * D_DIM];          // [s*B+b][2D]
__device__ float g_ctx [(size_t)T_DIM * B_DIM * D_DIM];              // [t][b][d]
__device__ half  g_feat_h[(size_t)T_DIM * B_DIM * KX];               // [tb][h|l]
__device__ half  g_wi_h  [(size_t)2 * D_DIM * KX];                   // [e][h|h]
__device__ half  g_wo_h  [(size_t)D_DIM * KX];                       // [e][h|h]
__device__ half  g_q_h   [(size_t)B_DIM * T_DIM * KX];               // [b][t][h|l]
__device__ half  g_k_h   [(size_t)B_DIM * T_DIM * KX];               // [b][s][h|h]
__device__ half  g_ctx_h [(size_t)T_DIM * B_DIM * KX];               // [tb][h|l]
__device__ half  g_p_h   [(size_t)B_DIM * T_DIM * T_DIM];            // [b][t][s]
__device__ half  g_vt_h  [(size_t)B_DIM * D_DIM * T_DIM];            // [b][d][s]

__device__ __forceinline__ uint32_t smem_u32(const void* p) {
    uint32_t a;
    asm("{ .reg .u64 t; cvta.to.shared.u64 t, %1; cvt.u32.u64 %0, t; }" : "=r"(a) : "l"(p));
    return a;
}

// ---------------------------------------------------------------------------
// fp16 NT GEMM via mma.sync, fp32 accum.
// 3-stage cp.async pipeline, 1 sync per k-tile. Block 128x128x32, 256 thr.
// ---------------------------------------------------------------------------
#define BM 128
#define BN 128
#define BK 32
#define PITCH 40
#define ABYTES (BM * PITCH * 2)
#define BBYTES (BN * PITCH * 2)
#define STAGE_BYTES (ABYTES + BBYTES)
#define GEMM_SMEM (3 * STAGE_BYTES)   // 61440

__global__ __launch_bounds__(256, 2) void gemm_mma_h(
    const half* __restrict__ A, long sAz, int lda,
    const half* __restrict__ B, long sBz, int ldb,
    float* __restrict__ C, long sCz, int ldc,
    const float* __restrict__ bias, int Kext)
{
    extern __shared__ char smem[];
    const uint32_t sbase = smem_u32(smem);

    const int tid  = threadIdx.x;
    const int wid  = tid >> 5;
    const int lane = tid & 31;
    const int wm = (wid >> 2) * 64;
    const int wn = (wid & 3) * 32;
    const int m0 = blockIdx.y * BM;
    const int n0 = blockIdx.x * BN;

    A += (long)blockIdx.z * sAz;
    B += (long)blockIdx.z * sBz;
    C += (long)blockIdx.z * sCz;

    const int ld_row = tid >> 2;
    const int ld_c   = (tid & 3) * 16;

    auto load_tiles = [&](int st, int k0) {
        const uint32_t a0 = sbase + st * STAGE_BYTES;
        const uint32_t b0 = a0 + ABYTES;
        #pragma unroll
        for (int h = 0; h < 2; h++) {
            const int row = ld_row + h * 64;
            const uint32_t da = a0 + row * (PITCH * 2) + ld_c;
            const half* ga = A + (size_t)(m0 + row) * lda + k0 + (ld_c >> 1);
            asm volatile("cp.async.cg.shared.global [%0], [%1], 16;" :: "r"(da), "l"(ga));
            const uint32_t db = b0 + row * (PITCH * 2) + ld_c;
            const half* gb = B + (size_t)(n0 + row) * ldb + k0 + (ld_c >> 1);
            asm volatile("cp.async.cg.shared.global [%0], [%1], 16;" :: "r"(db), "l"(gb));
        }
        asm volatile("cp.async.commit_group;" ::: "memory");
    };

    float acc[4][4][4];
    #pragma unroll
    for (int i = 0; i < 4; i++)
        #pragma unroll
        for (int j = 0; j < 4; j++)
            #pragma unroll
            for (int r = 0; r < 4; r++) acc[i][j][r] = 0.f;

    const int niter = Kext / BK;
    load_tiles(0, 0);
    load_tiles(1, BK);

    int st = 0;
    for (int kt = 0; kt < niter; kt++) {
        if (kt + 1 < niter) {
            asm volatile("cp.async.wait_group 1;" ::: "memory");
        } else {
            asm volatile("cp.async.wait_group 0;" ::: "memory");
        }
        __syncthreads();
        if (kt + 2 < niter) {
            int st2 = st + 2; if (st2 >= 3) st2 -= 3;
            load_tiles(st2, (kt + 2) * BK);
        }

        const uint32_t sA = sbase + st * STAGE_BYTES;
        const uint32_t sB = sA + ABYTES;

        #pragma unroll
        for (int k16 = 0; k16 < 2; k16++) {
            uint32_t af[4][4];
            #pragma unroll
            for (int mt = 0; mt < 4; mt++) {
                const int row = wm + mt * 16 + (lane & 15);
                const int col = (lane >> 4) * 8 + k16 * 16;
                const uint32_t addr = sA + row * (PITCH * 2) + col * 2;
                asm volatile("ldmatrix.sync.aligned.m8n8.x4.shared.b16 {%0,%1,%2,%3}, [%4];"
                             : "=r"(af[mt][0]), "=r"(af[mt][1]), "=r"(af[mt][2]), "=r"(af[mt][3])
                             : "r"(addr));
            }
            uint32_t bf[4][2];
            #pragma unroll
            for (int pr = 0; pr < 2; pr++) {
                const int row = wn + pr * 16 + ((lane >> 4) & 1) * 8 + (lane & 7);
                const int col = ((lane >> 3) & 1) * 8 + k16 * 16;
                const uint32_t addr = sB + row * (PITCH * 2) + col * 2;
                asm volatile("ldmatrix.sync.aligned.m8n8.x4.shared.b16 {%0,%1,%2,%3}, [%4];"
                             : "=r"(bf[pr * 2][0]), "=r"(bf[pr * 2][1]),
                               "=r"(bf[pr * 2 + 1][0]), "=r"(bf[pr * 2 + 1][1])
                             : "r"(addr));
            }
            #pragma unroll
            for (int mt = 0; mt < 4; mt++)
                #pragma unroll
                for (int nt = 0; nt < 4; nt++) {
                    asm volatile(
                        "mma.sync.aligned.m16n8k16.row.col.f32.f16.f16.f32 "
                        "{%0,%1,%2,%3}, {%4,%5,%6,%7}, {%8,%9}, {%0,%1,%2,%3};"
                        : "+f"(acc[mt][nt][0]), "+f"(acc[mt][nt][1]),
                          "+f"(acc[mt][nt][2]), "+f"(acc[mt][nt][3])
                        : "r"(af[mt][0]), "r"(af[mt][1]), "r"(af[mt][2]), "r"(af[mt][3]),
                          "r"(bf[nt][0]), "r"(bf[nt][1]));
                }
        }
        if (++st == 3) st = 0;
    }

    const int g  = lane >> 2;
    const int tg = lane & 3;
    #pragma unroll
    for (int mt = 0; mt < 4; mt++) {
        const int mrow0 = m0 + wm + mt * 16 + g;
        #pragma unroll
        for (int nt = 0; nt < 4; nt++) {
            const int n = n0 + wn + nt * 8 + 2 * tg;
            float b0 = 0.f, b1 = 0.f;
            if (bias) { b0 = bias[n]; b1 = bias[n + 1]; }
            float2 v0 = make_float2(acc[mt][nt][0] + b0, acc[mt][nt][1] + b1);
            float2 v1 = make_float2(acc[mt][nt][2] + b0, acc[mt][nt][3] + b1);
            *(float2*)(C + (size_t)mrow0 * ldc + n) = v0;
            *(float2*)(C + (size_t)(mrow0 + 8) * ldc + n) = v1;
        }
    }
}

// ---------------------------------------------------------------------------
// fp32 -> fp16 2-segment split.
//   modeA=1 (exact operand): [hi | lo]   lo = fp16(x - hi)
//   modeA=0 (rounded operand): [hi | hi]
// ---------------------------------------------------------------------------
__global__ __launch_bounds__(256) void split_conv_h(
    const float* __restrict__ src, long sb, long srs,
    half* __restrict__ dst, int rows, int K, float scale, int modeA)
{
    const long idx = (long)blockIdx.x * 256 + threadIdx.x;
    const int r = (int)(idx / K);
    const int k = (int)(idx % K);
    if (r >= rows) return;
    const float x = src[(long)blockIdx.z * sb + (long)r * srs + k] * scale;
    const half hi = __float2half_rn(x);
    half* d = dst + (size_t)blockIdx.z * rows * 2 * K + (size_t)r * 2 * K + k;
    d[0] = hi;
    d[K] = modeA ? __float2half_rn(x - __half2float(hi)) : hi;
}

// ---------------------------------------------------------------------------
// V transpose to fp16: kv V part [s*B+b][2D] -> vt_h[b][d][s]
// ---------------------------------------------------------------------------
__global__ __launch_bounds__(256) void vt_conv_h(
    const float* __restrict__ kv, half* __restrict__ vt)
{
    __shared__ float tile[32][33];
    const int b = blockIdx.z;
    const int s0 = blockIdx.x * 32;
    const int d0 = blockIdx.y * 32;
    const int tx = threadIdx.x & 31;
    const int ty = threadIdx.x >> 5;

    #pragma unroll
    for (int r = 0; r < 4; r++) {
        const int s = s0 + ty + r * 8;
        tile[ty + r * 8][tx] = kv[(size_t)s * (B_DIM * 2 * D_DIM) + b * (2 * D_DIM) + D_DIM + d0 + tx];
    }
    __syncthreads();
    #pragma unroll
    for (int r = 0; r < 4; r++) {
        const int d = d0 + ty + r * 8;
        const int s = s0 + tx;
        vt[(size_t)b * D_DIM * T_DIM + (size_t)d * T_DIM + s] = __float2half_rn(tile[tx][ty + r * 8]);
    }
}

// ---------------------------------------------------------------------------
// Softmax (in place, fp32) + fused fp16 P emission (coalesced)
// ---------------------------------------------------------------------------
__global__ __launch_bounds__(256) void softmax_p_kernel(
    float* __restrict__ P, half* __restrict__ ph_all)
{
    const long R = blockIdx.x;                  // b*T + t
    float* row = P + R * T_DIM;
    half* ph = ph_all + R * (size_t)T_DIM;
    const int tid = threadIdx.x;

    float vals[8];
    float mx = -INFINITY;
    #pragma unroll
    for (int i = 0; i < 8; i++) { vals[i] = row[tid + i * 256]; mx = fmaxf(mx, vals[i]); }

    __shared__ float red[256];
    red[tid] = mx; __syncthreads();
    for (int s = 128; s > 0; s >>= 1) { if (tid < s) red[tid] = fmaxf(red[tid], red[tid + s]); __syncthreads(); }
    mx = red[0]; __syncthreads();

    float sum = 0.f;
    #pragma unroll
    for (int i = 0; i < 8; i++) { vals[i] = __expf(vals[i] - mx); sum += vals[i]; }
    red[tid] = sum; __syncthreads();
    for (int s = 128; s > 0; s >>= 1) { if (tid < s) red[tid] += red[tid + s]; __syncthreads(); }
    const float inv = 1.0f / red[0];

    #pragma unroll
    for (int i = 0; i < 8; i++) {
        const int col = tid + i * 256;
        const float p = vals[i] * inv;
        row[col] = p;
        ph[col] = __float2half_rn(p);
    }
}

// ---------------------------------------------------------------------------
extern "C" void kernel_launch(void* const* d_in, const int* in_sizes, int n_in,
                              void* d_out, int out_size)
{
    const float* query = (const float*)d_in[0];
    const float* feat  = (const float*)d_in[1];
    const float* Wi    = (const float*)d_in[2];
    const float* bi    = (const float*)d_in[3];
    const float* Wo    = (const float*)d_in[4];
    const float* bo    = (const float*)d_in[5];

    float* out = (float*)d_out;
    float* attn_out = out;
    float* aw = out + (size_t)T_DIM * B_DIM * D_DIM;

    float *kv, *ctx;
    half *feat_h, *wi_h, *wo_h, *q_h, *k_h, *ctx_h, *p_h, *vt_h;
    cudaGetSymbolAddress((void**)&kv, g_kv);
    cudaGetSymbolAddress((void**)&ctx, g_ctx);
    cudaGetSymbolAddress((void**)&feat_h, g_feat_h);
    cudaGetSymbolAddress((void**)&wi_h, g_wi_h);
    cudaGetSymbolAddress((void**)&wo_h, g_wo_h);
    cudaGetSymbolAddress((void**)&q_h, g_q_h);
    cudaGetSymbolAddress((void**)&k_h, g_k_h);
    cudaGetSymbolAddress((void**)&ctx_h, g_ctx_h);
    cudaGetSymbolAddress((void**)&p_h, g_p_h);
    cudaGetSymbolAddress((void**)&vt_h, g_vt_h);

    cudaFuncSetAttribute(gemm_mma_h, cudaFuncAttributeMaxDynamicSharedMemorySize, GEMM_SMEM);

    const float scale = 0.03125f;   // D^-0.5
    const long TT = (long)T_DIM * T_DIM;

    // input conversions (fp16 split / dup)
    split_conv_h<<<dim3((T_DIM * B_DIM * D_DIM) / 256, 1, 1), 256>>>(feat, 0, D_DIM, feat_h, T_DIM * B_DIM, D_DIM, 1.f, 1);
    split_conv_h<<<dim3((2 * D_DIM * D_DIM) / 256, 1, 1), 256>>>(Wi, 0, D_DIM, wi_h, 2 * D_DIM, D_DIM, 1.f, 0);
    split_conv_h<<<dim3((D_DIM * D_DIM) / 256, 1, 1), 256>>>(Wo, 0, D_DIM, wo_h, D_DIM, D_DIM, 1.f, 0);
    split_conv_h<<<dim3((T_DIM * D_DIM) / 256, 1, B_DIM), 256>>>(query, D_DIM, (long)B_DIM * D_DIM, q_h, T_DIM, D_DIM, scale, 1);

    // 1) KV projection (M=8192, N=2048, K'=2048)
    gemm_mma_h<<<dim3(2 * D_DIM / BN, T_DIM * B_DIM / BM, 1), 256, GEMM_SMEM>>>(
        feat_h, 0, KX, wi_h, 0, KX, kv, 0, 2 * D_DIM, bi, KX);

    // k -> fp16 dup [h|h]; V -> transpose fp16
    split_conv_h<<<dim3((T_DIM * D_DIM) / 256, 1, B_DIM), 256>>>(kv, 2 * D_DIM, (long)B_DIM * 2 * D_DIM, k_h, T_DIM, D_DIM, 1.f, 0);
    vt_conv_h<<<dim3(T_DIM / 32, D_DIM / 32, B_DIM), 256>>>(kv, vt_h);

    // 2) scores (M=2048, N=2048, K'=2048), batched over B
    gemm_mma_h<<<dim3(T_DIM / BN, T_DIM / BM, B_DIM), 256, GEMM_SMEM>>>(
        q_h, (long)T_DIM * KX, KX, k_h, (long)T_DIM * KX, KX,
        aw, TT, T_DIM, nullptr, KX);

    // 3) softmax + fused fp16 P emission
    softmax_p_kernel<<<B_DIM * T_DIM, 256>>>(aw, p_h);

    // 4) context (M=2048, N=1024, K=2048) fp16 single, batched
    gemm_mma_h<<<dim3(D_DIM / BN, T_DIM / BM, B_DIM), 256, GEMM_SMEM>>>(
        p_h, TT, T_DIM, vt_h, (long)D_DIM * T_DIM, T_DIM,
        ctx, D_DIM, B_DIM * D_DIM, nullptr, T_DIM);

    // ctx -> fp16 split [h|l]
    split_conv_h<<<dim3((T_DIM * B_DIM * D_DIM) / 256, 1, 1), 256>>>(ctx, 0, D_DIM, ctx_h, T_DIM * B_DIM, D_DIM, 1.f, 1);

    // 5) out projection (M=8192, N=1024, K'=2048)
    gemm_mma_h<<<dim3(D_DIM / BN, T_DIM * B_DIM / BM, 1), 256, GEMM_SMEM>>>(
        ctx_h, 0, KX, wo_h, 0, KX, attn_out, 0, D_DIM, bo, KX);
}

// round 13
// speedup vs baseline: 4.3049x; 1.1047x over previous
#include <cuda_runtime.h>
#include <cuda_fp16.h>
#include <math.h>
#include <stdint.h>

#define T_DIM 2048
#define B_DIM 4
#define D_DIM 1024
#define KX (2 * D_DIM)        // 2048 -- K' for split-A GEMMs

// ---------------------------------------------------------------------------
// Device scratch
// ---------------------------------------------------------------------------
__device__ float g_v   [(size_t)T_DIM * B_DIM * D_DIM];              // [s*B+b][d] (V + bias)
__device__ half  g_feat_h[(size_t)T_DIM * B_DIM * KX];               // [tb][h|l]
__device__ half  g_wi_h  [(size_t)2 * D_DIM * D_DIM];                // [e][h]  (dedup)
__device__ half  g_wo_h  [(size_t)D_DIM * D_DIM];                    // [e][h]  (dedup)
__device__ half  g_q_h   [(size_t)B_DIM * T_DIM * KX];               // [b][t][h|l]
__device__ half  g_k_h   [(size_t)B_DIM * T_DIM * D_DIM];            // [b][s][h] (dedup)
__device__ half  g_ctx_h [(size_t)T_DIM * B_DIM * KX];               // [tb][h|l]
__device__ half  g_p_h   [(size_t)B_DIM * T_DIM * T_DIM];            // [b][t][s]
__device__ half  g_vt_h  [(size_t)B_DIM * D_DIM * T_DIM];            // [b][d][s]

__device__ __forceinline__ uint32_t smem_u32(const void* p) {
    uint32_t a;
    asm("{ .reg .u64 t; cvta.to.shared.u64 t, %1; cvt.u32.u64 %0, t; }" : "=r"(a) : "l"(p));
    return a;
}

// ---------------------------------------------------------------------------
// fp16 NT GEMM via mma.sync, fp32 accum. 3-stage cp.async, 1 sync/k-tile.
// B operand has logical length Kb; loader wraps (dedup of [h|h] layouts).
//   OMODE 0: C[m][n] = acc + bias[n]          (fp32 float2 stores)
//   OMODE 1: KV proj: n<D -> k_h fp16 (half2), n>=D -> g_v fp32; bias applied
//   OMODE 2: ctx:     ctx_h [h|l] two half2 stores; rows t -> (t*B+z)
// ---------------------------------------------------------------------------
#define BM 128
#define BN 128
#define BK 32
#define PITCH 40
#define ABYTES (BM * PITCH * 2)
#define BBYTES (BN * PITCH * 2)
#define STAGE_BYTES (ABYTES + BBYTES)
#define GEMM_SMEM (3 * STAGE_BYTES)   // 61440

template <int OMODE>
__global__ __launch_bounds__(256, 2) void gemm_mma_h(
    const half* __restrict__ A, long sAz, int lda,
    const half* __restrict__ B, long sBz, int ldb, int Kb,
    float* __restrict__ C, long sCz, int ldc,
    const float* __restrict__ bias,
    half* __restrict__ auxh, float* __restrict__ auxf, int Kext)
{
    extern __shared__ char smem[];
    const uint32_t sbase = smem_u32(smem);

    const int tid  = threadIdx.x;
    const int wid  = tid >> 5;
    const int lane = tid & 31;
    const int wm = (wid >> 2) * 64;
    const int wn = (wid & 3) * 32;
    const int m0 = blockIdx.y * BM;
    const int n0 = blockIdx.x * BN;
    const int zb = blockIdx.z;

    A += (long)zb * sAz;
    B += (long)zb * sBz;
    if (OMODE == 0) C += (long)zb * sCz;

    const int ld_row = tid >> 2;
    const int ld_c   = (tid & 3) * 16;

    auto load_tiles = [&](int st, int k0) {
        const int k0b = (k0 >= Kb) ? k0 - Kb : k0;
        const uint32_t a0 = sbase + st * STAGE_BYTES;
        const uint32_t b0 = a0 + ABYTES;
        #pragma unroll
        for (int h = 0; h < 2; h++) {
            const int row = ld_row + h * 64;
            const uint32_t da = a0 + row * (PITCH * 2) + ld_c;
            const half* ga = A + (size_t)(m0 + row) * lda + k0 + (ld_c >> 1);
            asm volatile("cp.async.cg.shared.global [%0], [%1], 16;" :: "r"(da), "l"(ga));
            const uint32_t db = b0 + row * (PITCH * 2) + ld_c;
            const half* gb = B + (size_t)(n0 + row) * ldb + k0b + (ld_c >> 1);
            asm volatile("cp.async.cg.shared.global [%0], [%1], 16;" :: "r"(db), "l"(gb));
        }
        asm volatile("cp.async.commit_group;" ::: "memory");
    };

    float acc[4][4][4];
    #pragma unroll
    for (int i = 0; i < 4; i++)
        #pragma unroll
        for (int j = 0; j < 4; j++)
            #pragma unroll
            for (int r = 0; r < 4; r++) acc[i][j][r] = 0.f;

    const int niter = Kext / BK;
    load_tiles(0, 0);
    load_tiles(1, BK);

    int st = 0;
    for (int kt = 0; kt < niter; kt++) {
        if (kt + 1 < niter) {
            asm volatile("cp.async.wait_group 1;" ::: "memory");
        } else {
            asm volatile("cp.async.wait_group 0;" ::: "memory");
        }
        __syncthreads();
        if (kt + 2 < niter) {
            int st2 = st + 2; if (st2 >= 3) st2 -= 3;
            load_tiles(st2, (kt + 2) * BK);
        }

        const uint32_t sA = sbase + st * STAGE_BYTES;
        const uint32_t sB = sA + ABYTES;

        #pragma unroll
        for (int k16 = 0; k16 < 2; k16++) {
            uint32_t af[4][4];
            #pragma unroll
            for (int mt = 0; mt < 4; mt++) {
                const int row = wm + mt * 16 + (lane & 15);
                const int col = (lane >> 4) * 8 + k16 * 16;
                const uint32_t addr = sA + row * (PITCH * 2) + col * 2;
                asm volatile("ldmatrix.sync.aligned.m8n8.x4.shared.b16 {%0,%1,%2,%3}, [%4];"
                             : "=r"(af[mt][0]), "=r"(af[mt][1]), "=r"(af[mt][2]), "=r"(af[mt][3])
                             : "r"(addr));
            }
            uint32_t bf[4][2];
            #pragma unroll
            for (int pr = 0; pr < 2; pr++) {
                const int row = wn + pr * 16 + ((lane >> 4) & 1) * 8 + (lane & 7);
                const int col = ((lane >> 3) & 1) * 8 + k16 * 16;
                const uint32_t addr = sB + row * (PITCH * 2) + col * 2;
                asm volatile("ldmatrix.sync.aligned.m8n8.x4.shared.b16 {%0,%1,%2,%3}, [%4];"
                             : "=r"(bf[pr * 2][0]), "=r"(bf[pr * 2][1]),
                               "=r"(bf[pr * 2 + 1][0]), "=r"(bf[pr * 2 + 1][1])
                             : "r"(addr));
            }
            #pragma unroll
            for (int mt = 0; mt < 4; mt++)
                #pragma unroll
                for (int nt = 0; nt < 4; nt++) {
                    asm volatile(
                        "mma.sync.aligned.m16n8k16.row.col.f32.f16.f16.f32 "
                        "{%0,%1,%2,%3}, {%4,%5,%6,%7}, {%8,%9}, {%0,%1,%2,%3};"
                        : "+f"(acc[mt][nt][0]), "+f"(acc[mt][nt][1]),
                          "+f"(acc[mt][nt][2]), "+f"(acc[mt][nt][3])
                        : "r"(af[mt][0]), "r"(af[mt][1]), "r"(af[mt][2]), "r"(af[mt][3]),
                          "r"(bf[nt][0]), "r"(bf[nt][1]));
                }
        }
        if (++st == 3) st = 0;
    }

    const int g  = lane >> 2;
    const int tg = lane & 3;

    if (OMODE == 0) {
        #pragma unroll
        for (int mt = 0; mt < 4; mt++) {
            const int mrow0 = m0 + wm + mt * 16 + g;
            #pragma unroll
            for (int nt = 0; nt < 4; nt++) {
                const int n = n0 + wn + nt * 8 + 2 * tg;
                float b0 = 0.f, b1 = 0.f;
                if (bias) { b0 = bias[n]; b1 = bias[n + 1]; }
                float2 v0 = make_float2(acc[mt][nt][0] + b0, acc[mt][nt][1] + b1);
                float2 v1 = make_float2(acc[mt][nt][2] + b0, acc[mt][nt][3] + b1);
                *(float2*)(C + (size_t)mrow0 * ldc + n) = v0;
                *(float2*)(C + (size_t)(mrow0 + 8) * ldc + n) = v1;
            }
        }
    } else if (OMODE == 1) {
        const bool isK = (n0 < D_DIM);
        #pragma unroll
        for (int mt = 0; mt < 4; mt++) {
            const int mrow0 = m0 + wm + mt * 16 + g;
            #pragma unroll
            for (int nt = 0; nt < 4; nt++) {
                const int n = n0 + wn + nt * 8 + 2 * tg;
                const float b0 = bias[n], b1 = bias[n + 1];
                const float v00 = acc[mt][nt][0] + b0, v01 = acc[mt][nt][1] + b1;
                const float v10 = acc[mt][nt][2] + b0, v11 = acc[mt][nt][3] + b1;
                if (isK) {
                    const int r0 = mrow0, r1 = mrow0 + 8;   // tb index
                    half2 h0; h0.x = __float2half_rn(v00); h0.y = __float2half_rn(v01);
                    half2 h1; h1.x = __float2half_rn(v10); h1.y = __float2half_rn(v11);
                    *(half2*)(auxh + ((size_t)(r0 & 3) * T_DIM + (r0 >> 2)) * D_DIM + n) = h0;
                    *(half2*)(auxh + ((size_t)(r1 & 3) * T_DIM + (r1 >> 2)) * D_DIM + n) = h1;
                } else {
                    *(float2*)(auxf + (size_t)mrow0 * D_DIM + (n - D_DIM)) = make_float2(v00, v01);
                    *(float2*)(auxf + (size_t)(mrow0 + 8) * D_DIM + (n - D_DIM)) = make_float2(v10, v11);
                }
            }
        }
    } else {  // OMODE == 2: ctx -> [h|l] fp16
        #pragma unroll
        for (int mt = 0; mt < 4; mt++) {
            const int mrow0 = m0 + wm + mt * 16 + g;
            #pragma unroll
            for (int nt = 0; nt < 4; nt++) {
                const int n = n0 + wn + nt * 8 + 2 * tg;
                #pragma unroll
                for (int rr = 0; rr < 2; rr++) {
                    const int t = mrow0 + rr * 8;
                    const float v0 = acc[mt][nt][rr * 2 + 0];
                    const float v1 = acc[mt][nt][rr * 2 + 1];
                    const half hi0 = __float2half_rn(v0);
                    const half hi1 = __float2half_rn(v1);
                    half2 hh; hh.x = hi0; hh.y = hi1;
                    half2 ll;
                    ll.x = __float2half_rn(v0 - __half2float(hi0));
                    ll.y = __float2half_rn(v1 - __half2float(hi1));
                    half* d = auxh + ((size_t)t * B_DIM + zb) * KX + n;
                    *(half2*)d = hh;
                    *(half2*)(d + D_DIM) = ll;
                }
            }
        }
    }
}

// ---------------------------------------------------------------------------
// fp32 -> fp16 conversion, 2 elems/thread.
//   modeA=1: [hi | lo] (row len 2K, exact split)   modeA=0: [hi] (row len K)
// ---------------------------------------------------------------------------
__global__ __launch_bounds__(256) void split_conv_h(
    const float* __restrict__ src, long sb, long srs,
    half* __restrict__ dst, int rows, int K, float scale, int modeA)
{
    const long idx = (long)blockIdx.x * 256 + threadIdx.x;
    const int K2 = K >> 1;
    const int r = (int)(idx / K2);
    const int k2 = (int)(idx % K2);
    if (r >= rows) return;
    const float2 x2 = *(const float2*)&src[(long)blockIdx.z * sb + (long)r * srs + 2 * k2];
    const float x0 = x2.x * scale, x1 = x2.y * scale;
    const half h0 = __float2half_rn(x0), h1 = __float2half_rn(x1);
    const int rowlen = modeA ? 2 * K : K;
    half* d = dst + (size_t)blockIdx.z * rows * rowlen + (size_t)r * rowlen + 2 * k2;
    half2 hh; hh.x = h0; hh.y = h1;
    *(half2*)d = hh;
    if (modeA) {
        half2 ll;
        ll.x = __float2half_rn(x0 - __half2float(h0));
        ll.y = __float2half_rn(x1 - __half2float(h1));
        *(half2*)(d + K) = ll;
    }
}

// ---------------------------------------------------------------------------
// V transpose to fp16: g_v[s*B+b][d] -> vt_h[b][d][s]
// ---------------------------------------------------------------------------
__global__ __launch_bounds__(256) void vt_conv_h(
    const float* __restrict__ V, half* __restrict__ vt)
{
    __shared__ float tile[32][33];
    const int b = blockIdx.z;
    const int s0 = blockIdx.x * 32;
    const int d0 = blockIdx.y * 32;
    const int tx = threadIdx.x & 31;
    const int ty = threadIdx.x >> 5;

    #pragma unroll
    for (int r = 0; r < 4; r++) {
        const int s = s0 + ty + r * 8;
        tile[ty + r * 8][tx] = V[((size_t)s * B_DIM + b) * D_DIM + d0 + tx];
    }
    __syncthreads();
    #pragma unroll
    for (int r = 0; r < 4; r++) {
        const int d = d0 + ty + r * 8;
        const int s = s0 + tx;
        vt[(size_t)b * D_DIM * T_DIM + (size_t)d * T_DIM + s] = __float2half_rn(tile[tx][ty + r * 8]);
    }
}

// ---------------------------------------------------------------------------
// Softmax (in place, fp32) + fused fp16 P emission (coalesced)
// ---------------------------------------------------------------------------
__global__ __launch_bounds__(256) void softmax_p_kernel(
    float* __restrict__ P, half* __restrict__ ph_all)
{
    const long R = blockIdx.x;
    float* row = P + R * T_DIM;
    half* ph = ph_all + R * (size_t)T_DIM;
    const int tid = threadIdx.x;

    float vals[8];
    float mx = -INFINITY;
    #pragma unroll
    for (int i = 0; i < 8; i++) { vals[i] = row[tid + i * 256]; mx = fmaxf(mx, vals[i]); }

    __shared__ float red[256];
    red[tid] = mx; __syncthreads();
    for (int s = 128; s > 0; s >>= 1) { if (tid < s) red[tid] = fmaxf(red[tid], red[tid + s]); __syncthreads(); }
    mx = red[0]; __syncthreads();

    float sum = 0.f;
    #pragma unroll
    for (int i = 0; i < 8; i++) { vals[i] = __expf(vals[i] - mx); sum += vals[i]; }
    red[tid] = sum; __syncthreads();
    for (int s = 128; s > 0; s >>= 1) { if (tid < s) red[tid] += red[tid + s]; __syncthreads(); }
    const float inv = 1.0f / red[0];

    #pragma unroll
    for (int i = 0; i < 8; i++) {
        const int col = tid + i * 256;
        const float p = vals[i] * inv;
        row[col] = p;
        ph[col] = __float2half_rn(p);
    }
}

// ---------------------------------------------------------------------------
extern "C" void kernel_launch(void* const* d_in, const int* in_sizes, int n_in,
                              void* d_out, int out_size)
{
    const float* query = (const float*)d_in[0];
    const float* feat  = (const float*)d_in[1];
    const float* Wi    = (const float*)d_in[2];
    const float* bi    = (const float*)d_in[3];
    const float* Wo    = (const float*)d_in[4];
    const float* bo    = (const float*)d_in[5];

    float* out = (float*)d_out;
    float* attn_out = out;
    float* aw = out + (size_t)T_DIM * B_DIM * D_DIM;

    float *gv;
    half *feat_h, *wi_h, *wo_h, *q_h, *k_h, *ctx_h, *p_h, *vt_h;
    cudaGetSymbolAddress((void**)&gv, g_v);
    cudaGetSymbolAddress((void**)&feat_h, g_feat_h);
    cudaGetSymbolAddress((void**)&wi_h, g_wi_h);
    cudaGetSymbolAddress((void**)&wo_h, g_wo_h);
    cudaGetSymbolAddress((void**)&q_h, g_q_h);
    cudaGetSymbolAddress((void**)&k_h, g_k_h);
    cudaGetSymbolAddress((void**)&ctx_h, g_ctx_h);
    cudaGetSymbolAddress((void**)&p_h, g_p_h);
    cudaGetSymbolAddress((void**)&vt_h, g_vt_h);

    cudaFuncSetAttribute(gemm_mma_h<0>, cudaFuncAttributeMaxDynamicSharedMemorySize, GEMM_SMEM);
    cudaFuncSetAttribute(gemm_mma_h<1>, cudaFuncAttributeMaxDynamicSharedMemorySize, GEMM_SMEM);
    cudaFuncSetAttribute(gemm_mma_h<2>, cudaFuncAttributeMaxDynamicSharedMemorySize, GEMM_SMEM);

    const float scale = 0.03125f;   // D^-0.5
    const long TT = (long)T_DIM * T_DIM;

    // input conversions (2 elems/thread)
    split_conv_h<<<dim3((T_DIM * B_DIM * D_DIM / 2) / 256, 1, 1), 256>>>(feat, 0, D_DIM, feat_h, T_DIM * B_DIM, D_DIM, 1.f, 1);
    split_conv_h<<<dim3((2 * D_DIM * D_DIM / 2) / 256, 1, 1), 256>>>(Wi, 0, D_DIM, wi_h, 2 * D_DIM, D_DIM, 1.f, 0);
    split_conv_h<<<dim3((D_DIM * D_DIM / 2) / 256, 1, 1), 256>>>(Wo, 0, D_DIM, wo_h, D_DIM, D_DIM, 1.f, 0);
    split_conv_h<<<dim3((T_DIM * D_DIM / 2) / 256, 1, B_DIM), 256>>>(query, D_DIM, (long)B_DIM * D_DIM, q_h, T_DIM, D_DIM, scale, 1);

    // 1) KV projection (M=8192, N=2048, K'=2048, Kb=1024); fused K fp16 + V fp32
    gemm_mma_h<1><<<dim3(2 * D_DIM / BN, T_DIM * B_DIM / BM, 1), 256, GEMM_SMEM>>>(
        feat_h, 0, KX, wi_h, 0, D_DIM, D_DIM,
        nullptr, 0, 0, bi, k_h, gv, KX);

    // V transpose to fp16
    vt_conv_h<<<dim3(T_DIM / 32, D_DIM / 32, B_DIM), 256>>>(gv, vt_h);

    // 2) scores (M=2048, N=2048, K'=2048, Kb=1024), batched over B
    gemm_mma_h<0><<<dim3(T_DIM / BN, T_DIM / BM, B_DIM), 256, GEMM_SMEM>>>(
        q_h, (long)T_DIM * KX, KX, k_h, (long)T_DIM * D_DIM, D_DIM, D_DIM,
        aw, TT, T_DIM, nullptr, nullptr, nullptr, KX);

    // 3) softmax + fused fp16 P emission
    softmax_p_kernel<<<B_DIM * T_DIM, 256>>>(aw, p_h);

    // 4) context (M=2048, N=1024, K=2048, Kb=2048), fused ctx [h|l]
    gemm_mma_h<2><<<dim3(D_DIM / BN, T_DIM / BM, B_DIM), 256, GEMM_SMEM>>>(
        p_h, TT, T_DIM, vt_h, (long)D_DIM * T_DIM, T_DIM, T_DIM,
        nullptr, 0, 0, nullptr, ctx_h, nullptr, T_DIM);

    // 5) out projection (M=8192, N=1024, K'=2048, Kb=1024)
    gemm_mma_h<0><<<dim3(D_DIM / BN, T_DIM * B_DIM / BM, 1), 256, GEMM_SMEM>>>(
        ctx_h, 0, KX, wo_h, 0, D_DIM, D_DIM,
        attn_out, 0, D_DIM, bo, nullptr, nullptr, KX);
}

// round 15
// speedup vs baseline: 4.9277x; 1.1447x over previous
#include <cuda_runtime.h>
#include <cuda_fp16.h>
#include <math.h>
#include <stdint.h>

#define T_DIM 2048
#define B_DIM 4
#define D_DIM 1024
#define KX (2 * D_DIM)        // 2048 -- K' for split-A GEMMs

// ---------------------------------------------------------------------------
// Device scratch
// ---------------------------------------------------------------------------
__device__ float g_v   [(size_t)T_DIM * B_DIM * D_DIM];              // [s*B+b][d] (V + bias)
__device__ half  g_feat_h[(size_t)T_DIM * B_DIM * KX];               // [tb][h|l]
__device__ half  g_wi_h  [(size_t)2 * D_DIM * D_DIM];                // [e][h]  (dedup)
__device__ half  g_wo_h  [(size_t)D_DIM * D_DIM];                    // [e][h]  (dedup)
__device__ half  g_q_h   [(size_t)B_DIM * T_DIM * D_DIM];            // [b][t][h]  (single)
__device__ half  g_k_h   [(size_t)B_DIM * T_DIM * D_DIM];            // [b][s][h] (dedup)
__device__ half  g_ctx_h [(size_t)T_DIM * B_DIM * KX];               // [tb][h|l]
__device__ half  g_p_h   [(size_t)B_DIM * T_DIM * T_DIM];            // [b][t][s]
__device__ half  g_vt_h  [(size_t)B_DIM * D_DIM * T_DIM];            // [b][d][s]

__device__ __forceinline__ uint32_t smem_u32(const void* p) {
    uint32_t a;
    asm("{ .reg .u64 t; cvta.to.shared.u64 t, %1; cvt.u32.u64 %0, t; }" : "=r"(a) : "l"(p));
    return a;
}

// ---------------------------------------------------------------------------
// fp16 NT GEMM via mma.sync, fp32 accum. 3-stage cp.async, 1 sync/k-tile.
// B operand has logical length Kb; loader wraps (dedup of [h|h] layouts).
//   OMODE 0: C[m][n] = acc + bias[n]          (fp32 float2 stores)
//   OMODE 1: KV proj: n<D -> k_h fp16 (half2), n>=D -> g_v fp32; bias applied
//   OMODE 2: ctx:     ctx_h [h|l] two half2 stores; rows t -> (t*B+z)
// ---------------------------------------------------------------------------
#define BM 128
#define BN 128
#define BK 32
#define PITCH 40
#define ABYTES (BM * PITCH * 2)
#define BBYTES (BN * PITCH * 2)
#define STAGE_BYTES (ABYTES + BBYTES)
#define GEMM_SMEM (3 * STAGE_BYTES)   // 61440

template <int OMODE>
__global__ __launch_bounds__(256, 2) void gemm_mma_h(
    const half* __restrict__ A, long sAz, int lda,
    const half* __restrict__ B, long sBz, int ldb, int Kb,
    float* __restrict__ C, long sCz, int ldc,
    const float* __restrict__ bias,
    half* __restrict__ auxh, float* __restrict__ auxf, int Kext)
{
    extern __shared__ char smem[];
    const uint32_t sbase = smem_u32(smem);

    const int tid  = threadIdx.x;
    const int wid  = tid >> 5;
    const int lane = tid & 31;
    const int wm = (wid >> 2) * 64;
    const int wn = (wid & 3) * 32;
    const int m0 = blockIdx.y * BM;
    const int n0 = blockIdx.x * BN;
    const int zb = blockIdx.z;

    A += (long)zb * sAz;
    B += (long)zb * sBz;
    if (OMODE == 0) C += (long)zb * sCz;

    const int ld_row = tid >> 2;
    const int ld_c   = (tid & 3) * 16;

    auto load_tiles = [&](int st, int k0) {
        const int k0b = (k0 >= Kb) ? k0 - Kb : k0;
        const uint32_t a0 = sbase + st * STAGE_BYTES;
        const uint32_t b0 = a0 + ABYTES;
        #pragma unroll
        for (int h = 0; h < 2; h++) {
            const int row = ld_row + h * 64;
            const uint32_t da = a0 + row * (PITCH * 2) + ld_c;
            const half* ga = A + (size_t)(m0 + row) * lda + k0 + (ld_c >> 1);
            asm volatile("cp.async.cg.shared.global [%0], [%1], 16;" :: "r"(da), "l"(ga));
            const uint32_t db = b0 + row * (PITCH * 2) + ld_c;
            const half* gb = B + (size_t)(n0 + row) * ldb + k0b + (ld_c >> 1);
            asm volatile("cp.async.cg.shared.global [%0], [%1], 16;" :: "r"(db), "l"(gb));
        }
        asm volatile("cp.async.commit_group;" ::: "memory");
    };

    float acc[4][4][4];
    #pragma unroll
    for (int i = 0; i < 4; i++)
        #pragma unroll
        for (int j = 0; j < 4; j++)
            #pragma unroll
            for (int r = 0; r < 4; r++) acc[i][j][r] = 0.f;

    const int niter = Kext / BK;
    load_tiles(0, 0);
    load_tiles(1, BK);

    int st = 0;
    for (int kt = 0; kt < niter; kt++) {
        if (kt + 1 < niter) {
            asm volatile("cp.async.wait_group 1;" ::: "memory");
        } else {
            asm volatile("cp.async.wait_group 0;" ::: "memory");
        }
        __syncthreads();
        if (kt + 2 < niter) {
            int st2 = st + 2; if (st2 >= 3) st2 -= 3;
            load_tiles(st2, (kt + 2) * BK);
        }

        const uint32_t sA = sbase + st * STAGE_BYTES;
        const uint32_t sB = sA + ABYTES;

        #pragma unroll
        for (int k16 = 0; k16 < 2; k16++) {
            uint32_t af[4][4];
            #pragma unroll
            for (int mt = 0; mt < 4; mt++) {
                const int row = wm + mt * 16 + (lane & 15);
                const int col = (lane >> 4) * 8 + k16 * 16;
                const uint32_t addr = sA + row * (PITCH * 2) + col * 2;
                asm volatile("ldmatrix.sync.aligned.m8n8.x4.shared.b16 {%0,%1,%2,%3}, [%4];"
                             : "=r"(af[mt][0]), "=r"(af[mt][1]), "=r"(af[mt][2]), "=r"(af[mt][3])
                             : "r"(addr));
            }
            uint32_t bf[4][2];
            #pragma unroll
            for (int pr = 0; pr < 2; pr++) {
                const int row = wn + pr * 16 + ((lane >> 4) & 1) * 8 + (lane & 7);
                const int col = ((lane >> 3) & 1) * 8 + k16 * 16;
                const uint32_t addr = sB + row * (PITCH * 2) + col * 2;
                asm volatile("ldmatrix.sync.aligned.m8n8.x4.shared.b16 {%0,%1,%2,%3}, [%4];"
                             : "=r"(bf[pr * 2][0]), "=r"(bf[pr * 2][1]),
                               "=r"(bf[pr * 2 + 1][0]), "=r"(bf[pr * 2 + 1][1])
                             : "r"(addr));
            }
            #pragma unroll
            for (int mt = 0; mt < 4; mt++)
                #pragma unroll
                for (int nt = 0; nt < 4; nt++) {
                    asm volatile(
                        "mma.sync.aligned.m16n8k16.row.col.f32.f16.f16.f32 "
                        "{%0,%1,%2,%3}, {%4,%5,%6,%7}, {%8,%9}, {%0,%1,%2,%3};"
                        : "+f"(acc[mt][nt][0]), "+f"(acc[mt][nt][1]),
                          "+f"(acc[mt][nt][2]), "+f"(acc[mt][nt][3])
                        : "r"(af[mt][0]), "r"(af[mt][1]), "r"(af[mt][2]), "r"(af[mt][3]),
                          "r"(bf[nt][0]), "r"(bf[nt][1]));
                }
        }
        if (++st == 3) st = 0;
    }

    const int g  = lane >> 2;
    const int tg = lane & 3;

    if (OMODE == 0) {
        #pragma unroll
        for (int mt = 0; mt < 4; mt++) {
            const int mrow0 = m0 + wm + mt * 16 + g;
            #pragma unroll
            for (int nt = 0; nt < 4; nt++) {
                const int n = n0 + wn + nt * 8 + 2 * tg;
                float b0 = 0.f, b1 = 0.f;
                if (bias) { b0 = bias[n]; b1 = bias[n + 1]; }
                float2 v0 = make_float2(acc[mt][nt][0] + b0, acc[mt][nt][1] + b1);
                float2 v1 = make_float2(acc[mt][nt][2] + b0, acc[mt][nt][3] + b1);
                *(float2*)(C + (size_t)mrow0 * ldc + n) = v0;
                *(float2*)(C + (size_t)(mrow0 + 8) * ldc + n) = v1;
            }
        }
    } else if (OMODE == 1) {
        const bool isK = (n0 < D_DIM);
        #pragma unroll
        for (int mt = 0; mt < 4; mt++) {
            const int mrow0 = m0 + wm + mt * 16 + g;
            #pragma unroll
            for (int nt = 0; nt < 4; nt++) {
                const int n = n0 + wn + nt * 8 + 2 * tg;
                const float b0 = bias[n], b1 = bias[n + 1];
                const float v00 = acc[mt][nt][0] + b0, v01 = acc[mt][nt][1] + b1;
                const float v10 = acc[mt][nt][2] + b0, v11 = acc[mt][nt][3] + b1;
                if (isK) {
                    const int r0 = mrow0, r1 = mrow0 + 8;   // tb index
                    half2 h0; h0.x = __float2half_rn(v00); h0.y = __float2half_rn(v01);
                    half2 h1; h1.x = __float2half_rn(v10); h1.y = __float2half_rn(v11);
                    *(half2*)(auxh + ((size_t)(r0 & 3) * T_DIM + (r0 >> 2)) * D_DIM + n) = h0;
                    *(half2*)(auxh + ((size_t)(r1 & 3) * T_DIM + (r1 >> 2)) * D_DIM + n) = h1;
                } else {
                    *(float2*)(auxf + (size_t)mrow0 * D_DIM + (n - D_DIM)) = make_float2(v00, v01);
                    *(float2*)(auxf + (size_t)(mrow0 + 8) * D_DIM + (n - D_DIM)) = make_float2(v10, v11);
                }
            }
        }
    } else {  // OMODE == 2: ctx -> [h|l] fp16
        #pragma unroll
        for (int mt = 0; mt < 4; mt++) {
            const int mrow0 = m0 + wm + mt * 16 + g;
            #pragma unroll
            for (int nt = 0; nt < 4; nt++) {
                const int n = n0 + wn + nt * 8 + 2 * tg;
                #pragma unroll
                for (int rr = 0; rr < 2; rr++) {
                    const int t = mrow0 + rr * 8;
                    const float v0 = acc[mt][nt][rr * 2 + 0];
                    const float v1 = acc[mt][nt][rr * 2 + 1];
                    const half hi0 = __float2half_rn(v0);
                    const half hi1 = __float2half_rn(v1);
                    half2 hh; hh.x = hi0; hh.y = hi1;
                    half2 ll;
                    ll.x = __float2half_rn(v0 - __half2float(hi0));
                    ll.y = __float2half_rn(v1 - __half2float(hi1));
                    half* d = auxh + ((size_t)t * B_DIM + zb) * KX + n;
                    *(half2*)d = hh;
                    *(half2*)(d + D_DIM) = ll;
                }
            }
        }
    }
}

// ---------------------------------------------------------------------------
// fp32 -> fp16 conversion, 2 elems/thread.
//   modeA=1: [hi | lo] (row len 2K, exact split)   modeA=0: [hi] (row len K)
// ---------------------------------------------------------------------------
__global__ __launch_bounds__(256) void split_conv_h(
    const float* __restrict__ src, long sb, long srs,
    half* __restrict__ dst, int rows, int K, float scale, int modeA)
{
    const long idx = (long)blockIdx.x * 256 + threadIdx.x;
    const int K2 = K >> 1;
    const int r = (int)(idx / K2);
    const int k2 = (int)(idx % K2);
    if (r >= rows) return;
    const float2 x2 = *(const float2*)&src[(long)blockIdx.z * sb + (long)r * srs + 2 * k2];
    const float x0 = x2.x * scale, x1 = x2.y * scale;
    const half h0 = __float2half_rn(x0), h1 = __float2half_rn(x1);
    const int rowlen = modeA ? 2 * K : K;
    half* d = dst + (size_t)blockIdx.z * rows * rowlen + (size_t)r * rowlen + 2 * k2;
    half2 hh; hh.x = h0; hh.y = h1;
    *(half2*)d = hh;
    if (modeA) {
        half2 ll;
        ll.x = __float2half_rn(x0 - __half2float(h0));
        ll.y = __float2half_rn(x1 - __half2float(h1));
        *(half2*)(d + K) = ll;
    }
}

// ---------------------------------------------------------------------------
// V transpose to fp16: g_v[s*B+b][d] -> vt_h[b][d][s]
// ---------------------------------------------------------------------------
__global__ __launch_bounds__(256) void vt_conv_h(
    const float* __restrict__ V, half* __restrict__ vt)
{
    __shared__ float tile[32][33];
    const int b = blockIdx.z;
    const int s0 = blockIdx.x * 32;
    const int d0 = blockIdx.y * 32;
    const int tx = threadIdx.x & 31;
    const int ty = threadIdx.x >> 5;

    #pragma unroll
    for (int r = 0; r < 4; r++) {
        const int s = s0 + ty + r * 8;
        tile[ty + r * 8][tx] = V[((size_t)s * B_DIM + b) * D_DIM + d0 + tx];
    }
    __syncthreads();
    #pragma unroll
    for (int r = 0; r < 4; r++) {
        const int d = d0 + ty + r * 8;
        const int s = s0 + tx;
        vt[(size_t)b * D_DIM * T_DIM + (size_t)d * T_DIM + s] = __float2half_rn(tile[tx][ty + r * 8]);
    }
}

// ---------------------------------------------------------------------------
// Softmax (in place, fp32) + fused fp16 P emission (coalesced)
// ---------------------------------------------------------------------------
__global__ __launch_bounds__(256) void softmax_p_kernel(
    float* __restrict__ P, half* __restrict__ ph_all)
{
    const long R = blockIdx.x;
    float* row = P + R * T_DIM;
    half* ph = ph_all + R * (size_t)T_DIM;
    const int tid = threadIdx.x;

    float vals[8];
    float mx = -INFINITY;
    #pragma unroll
    for (int i = 0; i < 8; i++) { vals[i] = row[tid + i * 256]; mx = fmaxf(mx, vals[i]); }

    __shared__ float red[256];
    red[tid] = mx; __syncthreads();
    for (int s = 128; s > 0; s >>= 1) { if (tid < s) red[tid] = fmaxf(red[tid], red[tid + s]); __syncthreads(); }
    mx = red[0]; __syncthreads();

    float sum = 0.f;
    #pragma unroll
    for (int i = 0; i < 8; i++) { vals[i] = __expf(vals[i] - mx); sum += vals[i]; }
    red[tid] = sum; __syncthreads();
    for (int s = 128; s > 0; s >>= 1) { if (tid < s) red[tid] += red[tid + s]; __syncthreads(); }
    const float inv = 1.0f / red[0];

    #pragma unroll
    for (int i = 0; i < 8; i++) {
        const int col = tid + i * 256;
        const float p = vals[i] * inv;
        row[col] = p;
        ph[col] = __float2half_rn(p);
    }
}

// ---------------------------------------------------------------------------
extern "C" void kernel_launch(void* const* d_in, const int* in_sizes, int n_in,
                              void* d_out, int out_size)
{
    const float* query = (const float*)d_in[0];
    const float* feat  = (const float*)d_in[1];
    const float* Wi    = (const float*)d_in[2];
    const float* bi    = (const float*)d_in[3];
    const float* Wo    = (const float*)d_in[4];
    const float* bo    = (const float*)d_in[5];

    float* out = (float*)d_out;
    float* attn_out = out;
    float* aw = out + (size_t)T_DIM * B_DIM * D_DIM;

    float *gv;
    half *feat_h, *wi_h, *wo_h, *q_h, *k_h, *ctx_h, *p_h, *vt_h;
    cudaGetSymbolAddress((void**)&gv, g_v);
    cudaGetSymbolAddress((void**)&feat_h, g_feat_h);
    cudaGetSymbolAddress((void**)&wi_h, g_wi_h);
    cudaGetSymbolAddress((void**)&wo_h, g_wo_h);
    cudaGetSymbolAddress((void**)&q_h, g_q_h);
    cudaGetSymbolAddress((void**)&k_h, g_k_h);
    cudaGetSymbolAddress((void**)&ctx_h, g_ctx_h);
    cudaGetSymbolAddress((void**)&p_h, g_p_h);
    cudaGetSymbolAddress((void**)&vt_h, g_vt_h);

    cudaFuncSetAttribute(gemm_mma_h<0>, cudaFuncAttributeMaxDynamicSharedMemorySize, GEMM_SMEM);
    cudaFuncSetAttribute(gemm_mma_h<1>, cudaFuncAttributeMaxDynamicSharedMemorySize, GEMM_SMEM);
    cudaFuncSetAttribute(gemm_mma_h<2>, cudaFuncAttributeMaxDynamicSharedMemorySize, GEMM_SMEM);

    const float scale = 0.03125f;   // D^-0.5
    const long TT = (long)T_DIM * T_DIM;

    // input conversions (2 elems/thread)
    split_conv_h<<<dim3((T_DIM * B_DIM * D_DIM / 2) / 256, 1, 1), 256>>>(feat, 0, D_DIM, feat_h, T_DIM * B_DIM, D_DIM, 1.f, 1);
    split_conv_h<<<dim3((2 * D_DIM * D_DIM / 2) / 256, 1, 1), 256>>>(Wi, 0, D_DIM, wi_h, 2 * D_DIM, D_DIM, 1.f, 0);
    split_conv_h<<<dim3((D_DIM * D_DIM / 2) / 256, 1, 1), 256>>>(Wo, 0, D_DIM, wo_h, D_DIM, D_DIM, 1.f, 0);
    // q: single rounded fp16 (R14 change -- drops the lo segment)
    split_conv_h<<<dim3((T_DIM * D_DIM / 2) / 256, 1, B_DIM), 256>>>(query, D_DIM, (long)B_DIM * D_DIM, q_h, T_DIM, D_DIM, scale, 0);

    // 1) KV projection (M=8192, N=2048, K'=2048, Kb=1024); fused K fp16 + V fp32
    gemm_mma_h<1><<<dim3(2 * D_DIM / BN, T_DIM * B_DIM / BM, 1), 256, GEMM_SMEM>>>(
        feat_h, 0, KX, wi_h, 0, D_DIM, D_DIM,
        nullptr, 0, 0, bi, k_h, gv, KX);

    // V transpose to fp16
    vt_conv_h<<<dim3(T_DIM / 32, D_DIM / 32, B_DIM), 256>>>(gv, vt_h);

    // 2) scores (M=2048, N=2048, K=1024, Kb=1024), batched over B
    gemm_mma_h<0><<<dim3(T_DIM / BN, T_DIM / BM, B_DIM), 256, GEMM_SMEM>>>(
        q_h, (long)T_DIM * D_DIM, D_DIM, k_h, (long)T_DIM * D_DIM, D_DIM, D_DIM,
        aw, TT, T_DIM, nullptr, nullptr, nullptr, D_DIM);

    // 3) softmax + fused fp16 P emission
    softmax_p_kernel<<<B_DIM * T_DIM, 256>>>(aw, p_h);

    // 4) context (M=2048, N=1024, K=2048, Kb=2048), fused ctx [h|l]
    gemm_mma_h<2><<<dim3(D_DIM / BN, T_DIM / BM, B_DIM), 256, GEMM_SMEM>>>(
        p_h, TT, T_DIM, vt_h, (long)D_DIM * T_DIM, T_DIM, T_DIM,
        nullptr, 0, 0, nullptr, ctx_h, nullptr, T_DIM);

    // 5) out projection (M=8192, N=1024, K'=2048, Kb=1024)
    gemm_mma_h<0><<<dim3(D_DIM / BN, T_DIM * B_DIM / BM, 1), 256, GEMM_SMEM>>>(
        ctx_h, 0, KX, wo_h, 0, D_DIM, D_DIM,
        attn_out, 0, D_DIM, bo, nullptr, nullptr, KX);
}

// round 17
// speedup vs baseline: 6.5886x; 1.3370x over previous
#include <cuda_runtime.h>
#include <cuda_fp16.h>
#include <math.h>
#include <stdint.h>

#define T_DIM 2048
#define B_DIM 4
#define D_DIM 1024

// ---------------------------------------------------------------------------
// Device scratch  (all GEMM operands now single-rounded fp16)
// ---------------------------------------------------------------------------
__device__ float g_v   [(size_t)T_DIM * B_DIM * D_DIM];              // [s*B+b][d] (V + bias)
__device__ half  g_feat_h[(size_t)T_DIM * B_DIM * D_DIM];            // [tb][h]
__device__ half  g_wi_h  [(size_t)2 * D_DIM * D_DIM];                // [e][h]
__device__ half  g_wo_h  [(size_t)D_DIM * D_DIM];                    // [e][h]
__device__ half  g_q_h   [(size_t)B_DIM * T_DIM * D_DIM];            // [b][t][h]
__device__ half  g_k_h   [(size_t)B_DIM * T_DIM * D_DIM];            // [b][s][h]
__device__ half  g_ctx_h [(size_t)T_DIM * B_DIM * D_DIM];            // [tb][h]
__device__ half  g_p_h   [(size_t)B_DIM * T_DIM * T_DIM];            // [b][t][s]
__device__ half  g_vt_h  [(size_t)B_DIM * D_DIM * T_DIM];            // [b][d][s]

__device__ __forceinline__ uint32_t smem_u32(const void* p) {
    uint32_t a;
    asm("{ .reg .u64 t; cvta.to.shared.u64 t, %1; cvt.u32.u64 %0, t; }" : "=r"(a) : "l"(p));
    return a;
}

// ---------------------------------------------------------------------------
// fp16 NT GEMM via mma.sync, fp32 accum. 3-stage cp.async, 1 sync/k-tile.
//   OMODE 0: C[m][n] = acc + bias[n]          (fp32 float2 stores)
//   OMODE 1: KV proj: n<D -> k_h fp16 (half2), n>=D -> g_v fp32; bias applied
//   OMODE 2: ctx:     ctx_h single fp16 half2 store; rows t -> (t*B+z)
// ---------------------------------------------------------------------------
#define BM 128
#define BN 128
#define BK 32
#define PITCH 40
#define ABYTES (BM * PITCH * 2)
#define BBYTES (BN * PITCH * 2)
#define STAGE_BYTES (ABYTES + BBYTES)
#define GEMM_SMEM (3 * STAGE_BYTES)   // 61440

template <int OMODE>
__global__ __launch_bounds__(256, 2) void gemm_mma_h(
    const half* __restrict__ A, long sAz, int lda,
    const half* __restrict__ B, long sBz, int ldb,
    float* __restrict__ C, long sCz, int ldc,
    const float* __restrict__ bias,
    half* __restrict__ auxh, float* __restrict__ auxf, int Kext)
{
    extern __shared__ char smem[];
    const uint32_t sbase = smem_u32(smem);

    const int tid  = threadIdx.x;
    const int wid  = tid >> 5;
    const int lane = tid & 31;
    const int wm = (wid >> 2) * 64;
    const int wn = (wid & 3) * 32;
    const int m0 = blockIdx.y * BM;
    const int n0 = blockIdx.x * BN;
    const int zb = blockIdx.z;

    A += (long)zb * sAz;
    B += (long)zb * sBz;
    if (OMODE == 0) C += (long)zb * sCz;

    const int ld_row = tid >> 2;
    const int ld_c   = (tid & 3) * 16;

    auto load_tiles = [&](int st, int k0) {
        const uint32_t a0 = sbase + st * STAGE_BYTES;
        const uint32_t b0 = a0 + ABYTES;
        #pragma unroll
        for (int h = 0; h < 2; h++) {
            const int row = ld_row + h * 64;
            const uint32_t da = a0 + row * (PITCH * 2) + ld_c;
            const half* ga = A + (size_t)(m0 + row) * lda + k0 + (ld_c >> 1);
            asm volatile("cp.async.cg.shared.global [%0], [%1], 16;" :: "r"(da), "l"(ga));
            const uint32_t db = b0 + row * (PITCH * 2) + ld_c;
            const half* gb = B + (size_t)(n0 + row) * ldb + k0 + (ld_c >> 1);
            asm volatile("cp.async.cg.shared.global [%0], [%1], 16;" :: "r"(db), "l"(gb));
        }
        asm volatile("cp.async.commit_group;" ::: "memory");
    };

    float acc[4][4][4];
    #pragma unroll
    for (int i = 0; i < 4; i++)
        #pragma unroll
        for (int j = 0; j < 4; j++)
            #pragma unroll
            for (int r = 0; r < 4; r++) acc[i][j][r] = 0.f;

    const int niter = Kext / BK;
    load_tiles(0, 0);
    load_tiles(1, BK);

    int st = 0;
    for (int kt = 0; kt < niter; kt++) {
        if (kt + 1 < niter) {
            asm volatile("cp.async.wait_group 1;" ::: "memory");
        } else {
            asm volatile("cp.async.wait_group 0;" ::: "memory");
        }
        __syncthreads();
        if (kt + 2 < niter) {
            int st2 = st + 2; if (st2 >= 3) st2 -= 3;
            load_tiles(st2, (kt + 2) * BK);
        }

        const uint32_t sA = sbase + st * STAGE_BYTES;
        const uint32_t sB = sA + ABYTES;

        #pragma unroll
        for (int k16 = 0; k16 < 2; k16++) {
            uint32_t af[4][4];
            #pragma unroll
            for (int mt = 0; mt < 4; mt++) {
                const int row = wm + mt * 16 + (lane & 15);
                const int col = (lane >> 4) * 8 + k16 * 16;
                const uint32_t addr = sA + row * (PITCH * 2) + col * 2;
                asm volatile("ldmatrix.sync.aligned.m8n8.x4.shared.b16 {%0,%1,%2,%3}, [%4];"
                             : "=r"(af[mt][0]), "=r"(af[mt][1]), "=r"(af[mt][2]), "=r"(af[mt][3])
                             : "r"(addr));
            }
            uint32_t bf[4][2];
            #pragma unroll
            for (int pr = 0; pr < 2; pr++) {
                const int row = wn + pr * 16 + ((lane >> 4) & 1) * 8 + (lane & 7);
                const int col = ((lane >> 3) & 1) * 8 + k16 * 16;
                const uint32_t addr = sB + row * (PITCH * 2) + col * 2;
                asm volatile("ldmatrix.sync.aligned.m8n8.x4.shared.b16 {%0,%1,%2,%3}, [%4];"
                             : "=r"(bf[pr * 2][0]), "=r"(bf[pr * 2][1]),
                               "=r"(bf[pr * 2 + 1][0]), "=r"(bf[pr * 2 + 1][1])
                             : "r"(addr));
            }
            #pragma unroll
            for (int mt = 0; mt < 4; mt++)
                #pragma unroll
                for (int nt = 0; nt < 4; nt++) {
                    asm volatile(
                        "mma.sync.aligned.m16n8k16.row.col.f32.f16.f16.f32 "
                        "{%0,%1,%2,%3}, {%4,%5,%6,%7}, {%8,%9}, {%0,%1,%2,%3};"
                        : "+f"(acc[mt][nt][0]), "+f"(acc[mt][nt][1]),
                          "+f"(acc[mt][nt][2]), "+f"(acc[mt][nt][3])
                        : "r"(af[mt][0]), "r"(af[mt][1]), "r"(af[mt][2]), "r"(af[mt][3]),
                          "r"(bf[nt][0]), "r"(bf[nt][1]));
                }
        }
        if (++st == 3) st = 0;
    }

    const int g  = lane >> 2;
    const int tg = lane & 3;

    if (OMODE == 0) {
        #pragma unroll
        for (int mt = 0; mt < 4; mt++) {
            const int mrow0 = m0 + wm + mt * 16 + g;
            #pragma unroll
            for (int nt = 0; nt < 4; nt++) {
                const int n = n0 + wn + nt * 8 + 2 * tg;
                float b0 = 0.f, b1 = 0.f;
                if (bias) { b0 = bias[n]; b1 = bias[n + 1]; }
                float2 v0 = make_float2(acc[mt][nt][0] + b0, acc[mt][nt][1] + b1);
                float2 v1 = make_float2(acc[mt][nt][2] + b0, acc[mt][nt][3] + b1);
                *(float2*)(C + (size_t)mrow0 * ldc + n) = v0;
                *(float2*)(C + (size_t)(mrow0 + 8) * ldc + n) = v1;
            }
        }
    } else if (OMODE == 1) {
        const bool isK = (n0 < D_DIM);
        #pragma unroll
        for (int mt = 0; mt < 4; mt++) {
            const int mrow0 = m0 + wm + mt * 16 + g;
            #pragma unroll
            for (int nt = 0; nt < 4; nt++) {
                const int n = n0 + wn + nt * 8 + 2 * tg;
                const float b0 = bias[n], b1 = bias[n + 1];
                const float v00 = acc[mt][nt][0] + b0, v01 = acc[mt][nt][1] + b1;
                const float v10 = acc[mt][nt][2] + b0, v11 = acc[mt][nt][3] + b1;
                if (isK) {
                    const int r0 = mrow0, r1 = mrow0 + 8;   // tb index
                    half2 h0; h0.x = __float2half_rn(v00); h0.y = __float2half_rn(v01);
                    half2 h1; h1.x = __float2half_rn(v10); h1.y = __float2half_rn(v11);
                    *(half2*)(auxh + ((size_t)(r0 & 3) * T_DIM + (r0 >> 2)) * D_DIM + n) = h0;
                    *(half2*)(auxh + ((size_t)(r1 & 3) * T_DIM + (r1 >> 2)) * D_DIM + n) = h1;
                } else {
                    *(float2*)(auxf + (size_t)mrow0 * D_DIM + (n - D_DIM)) = make_float2(v00, v01);
                    *(float2*)(auxf + (size_t)(mrow0 + 8) * D_DIM + (n - D_DIM)) = make_float2(v10, v11);
                }
            }
        }
    } else {  // OMODE == 2: ctx -> single fp16
        #pragma unroll
        for (int mt = 0; mt < 4; mt++) {
            const int mrow0 = m0 + wm + mt * 16 + g;
            #pragma unroll
            for (int nt = 0; nt < 4; nt++) {
                const int n = n0 + wn + nt * 8 + 2 * tg;
                #pragma unroll
                for (int rr = 0; rr < 2; rr++) {
                    const int t = mrow0 + rr * 8;
                    half2 hh;
                    hh.x = __float2half_rn(acc[mt][nt][rr * 2 + 0]);
                    hh.y = __float2half_rn(acc[mt][nt][rr * 2 + 1]);
                    *(half2*)(auxh + ((size_t)t * B_DIM + zb) * D_DIM + n) = hh;
                }
            }
        }
    }
}

// ---------------------------------------------------------------------------
// fp32 -> fp16 conversion (single rounded), 2 elems/thread.
// ---------------------------------------------------------------------------
__global__ __launch_bounds__(256) void conv_h(
    const float* __restrict__ src, long sb, long srs,
    half* __restrict__ dst, int rows, int K, float scale)
{
    const long idx = (long)blockIdx.x * 256 + threadIdx.x;
    const int K2 = K >> 1;
    const int r = (int)(idx / K2);
    const int k2 = (int)(idx % K2);
    if (r >= rows) return;
    const float2 x2 = *(const float2*)&src[(long)blockIdx.z * sb + (long)r * srs + 2 * k2];
    half2 hh;
    hh.x = __float2half_rn(x2.x * scale);
    hh.y = __float2half_rn(x2.y * scale);
    *(half2*)(dst + (size_t)blockIdx.z * rows * K + (size_t)r * K + 2 * k2) = hh;
}

// ---------------------------------------------------------------------------
// V transpose to fp16: g_v[s*B+b][d] -> vt_h[b][d][s]
// ---------------------------------------------------------------------------
__global__ __launch_bounds__(256) void vt_conv_h(
    const float* __restrict__ V, half* __restrict__ vt)
{
    __shared__ float tile[32][33];
    const int b = blockIdx.z;
    const int s0 = blockIdx.x * 32;
    const int d0 = blockIdx.y * 32;
    const int tx = threadIdx.x & 31;
    const int ty = threadIdx.x >> 5;

    #pragma unroll
    for (int r = 0; r < 4; r++) {
        const int s = s0 + ty + r * 8;
        tile[ty + r * 8][tx] = V[((size_t)s * B_DIM + b) * D_DIM + d0 + tx];
    }
    __syncthreads();
    #pragma unroll
    for (int r = 0; r < 4; r++) {
        const int d = d0 + ty + r * 8;
        const int s = s0 + tx;
        vt[(size_t)b * D_DIM * T_DIM + (size_t)d * T_DIM + s] = __float2half_rn(tile[tx][ty + r * 8]);
    }
}

// ---------------------------------------------------------------------------
// Softmax (in place, fp32) + fused fp16 P emission (coalesced)
// ---------------------------------------------------------------------------
__global__ __launch_bounds__(256) void softmax_p_kernel(
    float* __restrict__ P, half* __restrict__ ph_all)
{
    const long R = blockIdx.x;
    float* row = P + R * T_DIM;
    half* ph = ph_all + R * (size_t)T_DIM;
    const int tid = threadIdx.x;

    float vals[8];
    float mx = -INFINITY;
    #pragma unroll
    for (int i = 0; i < 8; i++) { vals[i] = row[tid + i * 256]; mx = fmaxf(mx, vals[i]); }

    __shared__ float red[256];
    red[tid] = mx; __syncthreads();
    for (int s = 128; s > 0; s >>= 1) { if (tid < s) red[tid] = fmaxf(red[tid], red[tid + s]); __syncthreads(); }
    mx = red[0]; __syncthreads();

    float sum = 0.f;
    #pragma unroll
    for (int i = 0; i < 8; i++) { vals[i] = __expf(vals[i] - mx); sum += vals[i]; }
    red[tid] = sum; __syncthreads();
    for (int s = 128; s > 0; s >>= 1) { if (tid < s) red[tid] += red[tid + s]; __syncthreads(); }
    const float inv = 1.0f / red[0];

    #pragma unroll
    for (int i = 0; i < 8; i++) {
        const int col = tid + i * 256;
        const float p = vals[i] * inv;
        row[col] = p;
        ph[col] = __float2half_rn(p);
    }
}

// ---------------------------------------------------------------------------
extern "C" void kernel_launch(void* const* d_in, const int* in_sizes, int n_in,
                              void* d_out, int out_size)
{
    const float* query = (const float*)d_in[0];
    const float* feat  = (const float*)d_in[1];
    const float* Wi    = (const float*)d_in[2];
    const float* bi    = (const float*)d_in[3];
    const float* Wo    = (const float*)d_in[4];
    const float* bo    = (const float*)d_in[5];

    float* out = (float*)d_out;
    float* attn_out = out;
    float* aw = out + (size_t)T_DIM * B_DIM * D_DIM;

    float *gv;
    half *feat_h, *wi_h, *wo_h, *q_h, *k_h, *ctx_h, *p_h, *vt_h;
    cudaGetSymbolAddress((void**)&gv, g_v);
    cudaGetSymbolAddress((void**)&feat_h, g_feat_h);
    cudaGetSymbolAddress((void**)&wi_h, g_wi_h);
    cudaGetSymbolAddress((void**)&wo_h, g_wo_h);
    cudaGetSymbolAddress((void**)&q_h, g_q_h);
    cudaGetSymbolAddress((void**)&k_h, g_k_h);
    cudaGetSymbolAddress((void**)&ctx_h, g_ctx_h);
    cudaGetSymbolAddress((void**)&p_h, g_p_h);
    cudaGetSymbolAddress((void**)&vt_h, g_vt_h);

    cudaFuncSetAttribute(gemm_mma_h<0>, cudaFuncAttributeMaxDynamicSharedMemorySize, GEMM_SMEM);
    cudaFuncSetAttribute(gemm_mma_h<1>, cudaFuncAttributeMaxDynamicSharedMemorySize, GEMM_SMEM);
    cudaFuncSetAttribute(gemm_mma_h<2>, cudaFuncAttributeMaxDynamicSharedMemorySize, GEMM_SMEM);

    const float scale = 0.03125f;   // D^-0.5
    const long TT = (long)T_DIM * T_DIM;

    // input conversions (single rounded fp16, 2 elems/thread)
    conv_h<<<dim3((T_DIM * B_DIM * D_DIM / 2) / 256, 1, 1), 256>>>(feat, 0, D_DIM, feat_h, T_DIM * B_DIM, D_DIM, 1.f);
    conv_h<<<dim3((2 * D_DIM * D_DIM / 2) / 256, 1, 1), 256>>>(Wi, 0, D_DIM, wi_h, 2 * D_DIM, D_DIM, 1.f);
    conv_h<<<dim3((D_DIM * D_DIM / 2) / 256, 1, 1), 256>>>(Wo, 0, D_DIM, wo_h, D_DIM, D_DIM, 1.f);
    conv_h<<<dim3((T_DIM * D_DIM / 2) / 256, 1, B_DIM), 256>>>(query, D_DIM, (long)B_DIM * D_DIM, q_h, T_DIM, D_DIM, scale);

    // 1) KV projection (M=8192, N=2048, K=1024); fused K fp16 + V fp32
    gemm_mma_h<1><<<dim3(2 * D_DIM / BN, T_DIM * B_DIM / BM, 1), 256, GEMM_SMEM>>>(
        feat_h, 0, D_DIM, wi_h, 0, D_DIM,
        nullptr, 0, 0, bi, k_h, gv, D_DIM);

    // V transpose to fp16
    vt_conv_h<<<dim3(T_DIM / 32, D_DIM / 32, B_DIM), 256>>>(gv, vt_h);

    // 2) scores (M=2048, N=2048, K=1024), batched over B
    gemm_mma_h<0><<<dim3(T_DIM / BN, T_DIM / BM, B_DIM), 256, GEMM_SMEM>>>(
        q_h, (long)T_DIM * D_DIM, D_DIM, k_h, (long)T_DIM * D_DIM, D_DIM,
        aw, TT, T_DIM, nullptr, nullptr, nullptr, D_DIM);

    // 3) softmax + fused fp16 P emission
    softmax_p_kernel<<<B_DIM * T_DIM, 256>>>(aw, p_h);

    // 4) context (M=2048, N=1024, K=2048), fused ctx single fp16
    gemm_mma_h<2><<<dim3(D_DIM / BN, T_DIM / BM, B_DIM), 256, GEMM_SMEM>>>(
        p_h, TT, T_DIM, vt_h, (long)D_DIM * T_DIM, T_DIM,
        nullptr, 0, 0, nullptr, ctx_h, nullptr, T_DIM);

    // 5) out projection (M=8192, N=1024, K=1024)
    gemm_mma_h<0><<<dim3(D_DIM / BN, T_DIM * B_DIM / BM, 1), 256, GEMM_SMEM>>>(
        ctx_h, 0, D_DIM, wo_h, 0, D_DIM,
        attn_out, 0, D_DIM, bo, nullptr, nullptr, D_DIM);
}